// round 9
// baseline (speedup 1.0000x reference)
#include <cuda_runtime.h>
#include <cuda_bf16.h>
#include <cstdint>

// Involution2D on GB300 — round 9: round-8 with k_rw_mma register fix
// (A chunks staged 2-deep LDG->STS instead of all-4-in-registers, which
// spilled). xi keeps the M=128 tile; k_inv unchanged.

#define BB   4
#define HH_  128
#define WW_  128
#define CC   256
#define CR   64
#define KKG  144
#define FF   256
#define NPIX (BB*HH_*WW_)   // 65536

__device__ __align__(16) float g_w_buf[(size_t)NPIX * KKG];
__device__ __align__(16) float g_xi_buf[(size_t)NPIX * FF];
__device__ __align__(16) unsigned int g_wiT_hi[256 * 128];   // [f][c/2]
__device__ __align__(16) unsigned int g_wiT_lo[256 * 128];
__device__ __align__(16) unsigned int g_wrT_hi[64 * 128];    // [n][c/2]
__device__ __align__(16) unsigned int g_wrT_lo[64 * 128];
__device__ __align__(16) unsigned int g_wsT_hi[144 * 32];    // [f][k/2]
__device__ __align__(16) unsigned int g_wsT_lo[144 * 32];

#define SW(o) ((o) ^ (((o) >> 3) & 0x70))

__device__ __forceinline__ uint32_t smem_to_u32(const void* p) {
    uint32_t a;
    asm("{ .reg .u64 t; cvta.to.shared.u64 t, %1; cvt.u32.u64 %0, t; }"
        : "=r"(a) : "l"(p));
    return a;
}
__device__ __forceinline__ uint32_t bf16x2_rn(float lo, float hi) {
    uint32_t r;
    asm("cvt.rn.bf16x2.f32 %0, %1, %2;" : "=r"(r) : "f"(hi), "f"(lo));
    return r;
}
__device__ __forceinline__ void split2(float a, float b, uint32_t &hi, uint32_t &lo) {
    uint32_t ua = __float_as_uint(a), ub = __float_as_uint(b);
    hi = __byte_perm(ua, ub, 0x7632);
    lo = bf16x2_rn(a - __uint_as_float(ua & 0xFFFF0000u),
                   b - __uint_as_float(ub & 0xFFFF0000u));
}
__device__ __forceinline__ void cp_async16(uint32_t dst, const void* src) {
    asm volatile("{ .reg .u64 g; cvta.to.global.u64 g, %1;\n\t"
                 "cp.async.cg.shared.global [%0], [g], 16; }"
                 :: "r"(dst), "l"(src) : "memory");
}
__device__ __forceinline__ void cp_async16_z(uint32_t dst, const void* src, int sz) {
    asm volatile("{ .reg .u64 g; cvta.to.global.u64 g, %1;\n\t"
                 "cp.async.cg.shared.global [%0], [g], 16, %2; }"
                 :: "r"(dst), "l"(src), "r"(sz) : "memory");
}
#define CP_COMMIT() asm volatile("cp.async.commit_group;" ::: "memory")
#define CP_WAIT(n)  asm volatile("cp.async.wait_group %0;" :: "n"(n) : "memory")

__device__ __forceinline__ void ldsm4(uint32_t (&r)[4], const void* p) {
    uint32_t addr;
    asm("{ .reg .u64 t; cvta.to.shared.u64 t, %1; cvt.u32.u64 %0, t; }"
        : "=r"(addr) : "l"(p));
    asm volatile("ldmatrix.sync.aligned.m8n8.x4.shared.b16 {%0,%1,%2,%3}, [%4];"
                 : "=r"(r[0]), "=r"(r[1]), "=r"(r[2]), "=r"(r[3]) : "r"(addr));
}
__device__ __forceinline__ void mma16816(float (&d)[4], const uint32_t (&a)[4],
                                         uint32_t b0, uint32_t b1) {
    asm volatile(
        "mma.sync.aligned.m16n8k16.row.col.f32.bf16.bf16.f32 "
        "{%0,%1,%2,%3}, {%4,%5,%6,%7}, {%8,%9}, {%0,%1,%2,%3};"
        : "+f"(d[0]), "+f"(d[1]), "+f"(d[2]), "+f"(d[3])
        : "r"(a[0]), "r"(a[1]), "r"(a[2]), "r"(a[3]), "r"(b0), "r"(b1));
}

// ---------------- prep: weight transposes + hi/lo (22 blocks) ----------------
__global__ void __launch_bounds__(256)
k_prepw(const float* __restrict__ Wi, const float* __restrict__ Wr,
        const float* __restrict__ Ws)
{
    const int bid = blockIdx.x;
    const int t   = threadIdx.x;
    if (bid < 16) {
        const int idx = bid * 256 + t;
        for (int i = idx; i < 32768; i += 4096) {
            int f = i >> 7, cp = i & 127;
            uint32_t hi, lo;
            split2(Wi[(size_t)(2 * cp) * 256 + f],
                   Wi[(size_t)(2 * cp + 1) * 256 + f], hi, lo);
            g_wiT_hi[f * 128 + cp] = hi;
            g_wiT_lo[f * 128 + cp] = lo;
        }
    } else if (bid < 20) {
        const int idx = (bid - 16) * 256 + t;
        for (int i = idx; i < 8192; i += 1024) {
            int n = i >> 7, kp = i & 127;
            uint32_t hi, lo;
            split2(Wr[(2 * kp) * 64 + n], Wr[(2 * kp + 1) * 64 + n], hi, lo);
            g_wrT_hi[n * 128 + kp] = hi;
            g_wrT_lo[n * 128 + kp] = lo;
        }
    } else {
        const int idx = (bid - 20) * 256 + t;
        for (int i = idx; i < 4608; i += 512) {
            int f = i >> 5, kp = i & 31;
            uint32_t hi, lo;
            split2(Ws[(2 * kp) * 144 + f], Ws[(2 * kp + 1) * 144 + f], hi, lo);
            g_wsT_hi[f * 32 + kp] = hi;
            g_wsT_lo[f * 32 + kp] = lo;
        }
    }
}

// ---------------- kernel: xi = x @ Wi + bi, M=128, 512 threads ----------------
#define XG_A_HI 0
#define XG_A_LO 16384
#define XG_B_HI 32768
#define XG_B_LO 65536
#define XG_BUF  98304
#define XG_SMEM (2 * XG_BUF)   // 196608

__device__ __forceinline__ void xi_issue_B(uint32_t sb, int buf, int kb, int t)
{
    const uint32_t base = sb + buf * XG_BUF;
    const uint4* gbh = (const uint4*)g_wiT_hi;
    const uint4* gbl = (const uint4*)g_wiT_lo;
    #pragma unroll
    for (int it = 0; it < 4; ++it) {          // 256 rows x 8 x 16B
        int gi = t + it * 512;
        int f = gi >> 3, c = gi & 7;
        int src = f * 32 + kb * 8 + c;
        uint32_t d = SW(f * 128 + c * 16);
        cp_async16(base + XG_B_HI + d, gbh + src);
        cp_async16(base + XG_B_LO + d, gbl + src);
    }
}
__device__ __forceinline__ void xi_ldg_A(const float* __restrict__ x, int p0,
                                         int kb, int t, float4 (&rA)[4])
{
    const float4* xs = (const float4*)x;
    #pragma unroll
    for (int it = 0; it < 4; ++it) {
        int gi = t + it * 512;
        int row = gi >> 4, c4 = gi & 15;      // 128 rows x 16 float4
        rA[it] = xs[(size_t)(p0 + row) * 64 + kb * 16 + c4];
    }
}
__device__ __forceinline__ void xi_sts_A(char* smc, int buf, int t,
                                         const float4 (&rA)[4])
{
    char* base = smc + buf * XG_BUF;
    #pragma unroll
    for (int it = 0; it < 4; ++it) {
        int gi = t + it * 512;
        int row = gi >> 4, c4 = gi & 15;
        uint32_t h0, l0, h1, l1;
        split2(rA[it].x, rA[it].y, h0, l0);
        split2(rA[it].z, rA[it].w, h1, l1);
        uint32_t d = SW(row * 128 + c4 * 8);
        *(uint2*)(base + XG_A_HI + d) = make_uint2(h0, h1);
        *(uint2*)(base + XG_A_LO + d) = make_uint2(l0, l1);
    }
}

__global__ void __launch_bounds__(512, 1)
k_xi_mma(const float* __restrict__ x, const float* __restrict__ bi)
{
    extern __shared__ char smc[];
    const uint32_t sb = smem_to_u32(smc);
    const int t    = threadIdx.x;
    const int wid  = t >> 5;
    const int lane = t & 31;
    const int p0   = blockIdx.x * 128;
    const int wm   = wid >> 2;           // 0..3
    const int wn   = wid & 3;            // 0..3

    float4 rA[4];

    xi_ldg_A(x, p0, 0, t, rA);
    xi_issue_B(sb, 0, 0, t); CP_COMMIT();
    xi_sts_A(smc, 0, t, rA);
    xi_ldg_A(x, p0, 1, t, rA);
    xi_issue_B(sb, 1, 1, t); CP_COMMIT();
    xi_sts_A(smc, 1, t, rA);
    xi_ldg_A(x, p0, 2, t, rA);

    float acc[2][8][4];
    #pragma unroll
    for (int i = 0; i < 2; ++i)
        #pragma unroll
        for (int j = 0; j < 8; ++j)
            #pragma unroll
            for (int q = 0; q < 4; ++q) acc[i][j][q] = 0.f;

    const int lr   = lane & 15;
    const int lk   = (lane >> 4) * 16;
    const int arow = wm * 32 + lr;
    const int brow = wn * 64 + lr;

    for (int kb = 0; kb < 4; ++kb) {
        if (kb < 3) CP_WAIT(1); else CP_WAIT(0);
        __syncthreads();
        char* base = smc + (kb & 1) * XG_BUF;
        #pragma unroll
        for (int k16 = 0; k16 < 4; ++k16) {
            const int ko = k16 * 32 + lk;
            uint32_t ah[2][4], al[2][4];
            #pragma unroll
            for (int i = 0; i < 2; ++i) {
                ldsm4(ah[i], base + XG_A_HI + SW((arow + i * 16) * 128 + ko));
                ldsm4(al[i], base + XG_A_LO + SW((arow + i * 16) * 128 + ko));
            }
            #pragma unroll
            for (int j = 0; j < 4; ++j) {
                uint32_t bh[4], bl[4];
                ldsm4(bh, base + XG_B_HI + SW((brow + j * 16) * 128 + ko));
                ldsm4(bl, base + XG_B_LO + SW((brow + j * 16) * 128 + ko));
                #pragma unroll
                for (int i = 0; i < 2; ++i) {
                    mma16816(acc[i][2*j],   ah[i], bh[0], bh[2]);
                    mma16816(acc[i][2*j+1], ah[i], bh[1], bh[3]);
                    mma16816(acc[i][2*j],   al[i], bh[0], bh[2]);
                    mma16816(acc[i][2*j+1], al[i], bh[1], bh[3]);
                    mma16816(acc[i][2*j],   ah[i], bl[0], bl[2]);
                    mma16816(acc[i][2*j+1], ah[i], bl[1], bl[3]);
                }
            }
        }
        __syncthreads();
        if (kb + 2 < 4) {
            xi_sts_A(smc, kb & 1, t, rA);          // rA holds chunk kb+2
            xi_issue_B(sb, kb & 1, kb + 2, t); CP_COMMIT();
            if (kb + 3 < 4) xi_ldg_A(x, p0, kb + 3, t, rA);
        }
    }

    const int g  = lane >> 2;
    const int t2 = (lane & 3) * 2;
    #pragma unroll
    for (int i = 0; i < 2; ++i) {
        const int m = p0 + wm * 32 + i * 16 + g;
        #pragma unroll
        for (int j = 0; j < 8; ++j) {
            const int n = wn * 64 + j * 8 + t2;
            float b0 = bi[n], b1 = bi[n + 1];
            *(float2*)&g_xi_buf[(size_t)m * 256 + n] =
                make_float2(acc[i][j][0] + b0, acc[i][j][1] + b1);
            *(float2*)&g_xi_buf[(size_t)(m + 8) * 256 + n] =
                make_float2(acc[i][j][2] + b0, acc[i][j][3] + b1);
        }
    }
}

// ---------------- kernel: r+w fused; A staged 2-deep from x fp32 ----------------
#define RW_WS_HI 0
#define RW_WS_LO 18432
#define RW_SC    36864
#define RW_SH    37120
#define RW_A_HI  37376     // 4 chunks x 8192
#define RW_A_LO  70144
#define RW_B_HI  102912
#define RW_B_LO  135680
#define RW_R_HI  168448
#define RW_R_LO  176640
#define RW_SMEM  184832

__device__ __forceinline__ void rw_ldg_A(const float* __restrict__ x, int p0,
                                         int kb, int t, float4 (&rA)[4])
{
    const float4* xs = (const float4*)x;
    #pragma unroll
    for (int it = 0; it < 4; ++it) {
        int gi = t + it * 256;
        int row = gi >> 4, c4 = gi & 15;      // 64 rows x 16 float4
        rA[it] = xs[(size_t)(p0 + row) * 64 + kb * 16 + c4];
    }
}
__device__ __forceinline__ void rw_sts_A(char* smc, int kb, int t,
                                         const float4 (&rA)[4])
{
    #pragma unroll
    for (int it = 0; it < 4; ++it) {
        int gi = t + it * 256;
        int row = gi >> 4, c4 = gi & 15;
        uint32_t h0, l0, h1, l1;
        split2(rA[it].x, rA[it].y, h0, l0);
        split2(rA[it].z, rA[it].w, h1, l1);
        uint32_t d = kb * 8192 + SW(row * 128 + c4 * 8);
        *(uint2*)(smc + RW_A_HI + d) = make_uint2(h0, h1);
        *(uint2*)(smc + RW_A_LO + d) = make_uint2(l0, l1);
    }
}

__global__ void __launch_bounds__(256, 1)
k_rw_mma(const float* __restrict__ x,
         const float* __restrict__ br,   const float* __restrict__ gamma,
         const float* __restrict__ beta, const float* __restrict__ mean,
         const float* __restrict__ var,  const float* __restrict__ bs)
{
    extern __shared__ char smc[];
    const uint32_t sb = smem_to_u32(smc);
    const int t    = threadIdx.x;
    const int wid  = t >> 5;
    const int lane = t & 31;
    const int p0   = blockIdx.x * 64;
    const int wm   = wid >> 2;
    const int wn   = wid & 3;

    // group 0: resident WsT hi/lo (in flight during A LDG chain)
    {
        const uint4* sh = (const uint4*)g_wsT_hi;
        const uint4* sl = (const uint4*)g_wsT_lo;
        for (int i = t; i < 1152; i += 256) {
            int f = i >> 3, c = i & 7;
            uint32_t d = SW(f * 128 + c * 16);
            cp_async16(sb + RW_WS_HI + d, sh + i);
            cp_async16(sb + RW_WS_LO + d, sl + i);
        }
    }
    CP_COMMIT();
    // groups 1..4: WrT B chunks
    {
        const uint4* grh = (const uint4*)g_wrT_hi;
        const uint4* grl = (const uint4*)g_wrT_lo;
        #pragma unroll
        for (int kb = 0; kb < 4; ++kb) {
            #pragma unroll
            for (int it = 0; it < 2; ++it) {
                int gi = t + it * 256;
                int n = gi >> 3, c = gi & 7;
                int src = n * 32 + kb * 8 + c;
                uint32_t d = kb * 8192 + SW(n * 128 + c * 16);
                cp_async16(sb + RW_B_HI + d, grh + src);
                cp_async16(sb + RW_B_LO + d, grl + src);
            }
            CP_COMMIT();
        }
    }
    // A chunks: 2-deep LDG->convert->STS rotation (32 regs, no spills)
    {
        float4 rA0[4], rA1[4];
        rw_ldg_A(x, p0, 0, t, rA0);
        rw_ldg_A(x, p0, 1, t, rA1);
        rw_sts_A(smc, 0, t, rA0);
        rw_ldg_A(x, p0, 2, t, rA0);
        rw_sts_A(smc, 1, t, rA1);
        rw_ldg_A(x, p0, 3, t, rA1);
        rw_sts_A(smc, 2, t, rA0);
        rw_sts_A(smc, 3, t, rA1);
    }
    // BN constants
    if (t < 64) {
        float s = gamma[t] * rsqrtf(var[t] + 1e-3f);
        *(float*)(smc + RW_SC + t * 4) = s;
        *(float*)(smc + RW_SH + t * 4) = (br[t] - mean[t]) * s + beta[t];
    }

    const int lr    = lane & 15;
    const int lk    = (lane >> 4) * 16;
    const int arow  = wm * 32 + lr;
    const int brow1 = wn * 16 + lr;

    // ---- GEMM1: x @ Wr  (N=64, K=256) ----
    float acc1[2][2][4];
    #pragma unroll
    for (int i = 0; i < 2; ++i)
        #pragma unroll
        for (int j = 0; j < 2; ++j)
            #pragma unroll
            for (int q = 0; q < 4; ++q) acc1[i][j][q] = 0.f;

    #pragma unroll
    for (int kb = 0; kb < 4; ++kb) {
        if      (kb == 0) CP_WAIT(3);
        else if (kb == 1) CP_WAIT(2);
        else if (kb == 2) CP_WAIT(1);
        else              CP_WAIT(0);
        __syncthreads();
        char* abase  = smc + RW_A_HI + kb * 8192;
        char* albase = smc + RW_A_LO + kb * 8192;
        char* bbase  = smc + RW_B_HI + kb * 8192;
        char* blbase = smc + RW_B_LO + kb * 8192;
        #pragma unroll
        for (int k16 = 0; k16 < 4; ++k16) {
            const int ko = k16 * 32 + lk;
            uint32_t ah[2][4], al[2][4], bh[4], bl[4];
            #pragma unroll
            for (int i = 0; i < 2; ++i) {
                ldsm4(ah[i], abase  + SW((arow + i * 16) * 128 + ko));
                ldsm4(al[i], albase + SW((arow + i * 16) * 128 + ko));
            }
            ldsm4(bh, bbase  + SW(brow1 * 128 + ko));
            ldsm4(bl, blbase + SW(brow1 * 128 + ko));
            #pragma unroll
            for (int i = 0; i < 2; ++i) {
                mma16816(acc1[i][0], ah[i], bh[0], bh[2]);
                mma16816(acc1[i][1], ah[i], bh[1], bh[3]);
                mma16816(acc1[i][0], al[i], bh[0], bh[2]);
                mma16816(acc1[i][1], al[i], bh[1], bh[3]);
                mma16816(acc1[i][0], ah[i], bl[0], bl[2]);
                mma16816(acc1[i][1], ah[i], bl[1], bl[3]);
            }
        }
    }

    // ---- epilogue 1: BN + relu, split r -> smem hi/lo ----
    {
        const int g  = lane >> 2;
        const int t2 = (lane & 3) * 2;
        #pragma unroll
        for (int i = 0; i < 2; ++i) {
            #pragma unroll
            for (int n8 = 0; n8 < 2; ++n8) {
                const int n0 = wn * 16 + n8 * 8 + t2;
                const float s0 = *(float*)(smc + RW_SC + n0 * 4);
                const float s1 = *(float*)(smc + RW_SC + (n0 + 1) * 4);
                const float h0 = *(float*)(smc + RW_SH + n0 * 4);
                const float h1 = *(float*)(smc + RW_SH + (n0 + 1) * 4);
                #pragma unroll
                for (int half = 0; half < 2; ++half) {
                    const int m = wm * 32 + i * 16 + g + half * 8;
                    float r0 = fmaxf(fmaf(acc1[i][n8][half * 2],     s0, h0), 0.f);
                    float r1 = fmaxf(fmaf(acc1[i][n8][half * 2 + 1], s1, h1), 0.f);
                    uint32_t hi, lo;
                    split2(r0, r1, hi, lo);
                    uint32_t d = SW(m * 128 + n0 * 2);
                    *(uint32_t*)(smc + RW_R_HI + d) = hi;
                    *(uint32_t*)(smc + RW_R_LO + d) = lo;
                }
            }
        }
    }
    __syncthreads();

    // ---- GEMM2: w = r @ Ws + bs  (N=144, K=64) ----
    const int nblk = (wn == 3) ? 3 : 2;
    int blkid[3] = {wn, wn + 4, 8};
    float acc2[3][2][2][4];
    #pragma unroll
    for (int b = 0; b < 3; ++b)
        #pragma unroll
        for (int i = 0; i < 2; ++i)
            #pragma unroll
            for (int j = 0; j < 2; ++j)
                #pragma unroll
                for (int q = 0; q < 4; ++q) acc2[b][i][j][q] = 0.f;

    #pragma unroll
    for (int k16 = 0; k16 < 4; ++k16) {
        const int ko = k16 * 32 + lk;
        uint32_t ah[2][4], al[2][4];
        #pragma unroll
        for (int i = 0; i < 2; ++i) {
            ldsm4(ah[i], smc + RW_R_HI + SW((arow + i * 16) * 128 + ko));
            ldsm4(al[i], smc + RW_R_LO + SW((arow + i * 16) * 128 + ko));
        }
        for (int b = 0; b < nblk; ++b) {
            const int brow = blkid[b] * 16 + lr;
            uint32_t bh[4], bl[4];
            ldsm4(bh, smc + RW_WS_HI + SW(brow * 128 + ko));
            ldsm4(bl, smc + RW_WS_LO + SW(brow * 128 + ko));
            #pragma unroll
            for (int i = 0; i < 2; ++i) {
                mma16816(acc2[b][i][0], ah[i], bh[0], bh[2]);
                mma16816(acc2[b][i][1], ah[i], bh[1], bh[3]);
                mma16816(acc2[b][i][0], al[i], bh[0], bh[2]);
                mma16816(acc2[b][i][1], al[i], bh[1], bh[3]);
                mma16816(acc2[b][i][0], ah[i], bl[0], bl[2]);
                mma16816(acc2[b][i][1], ah[i], bl[1], bl[3]);
            }
        }
    }

    // ---- epilogue 2: w -> g_w_buf (+bs) ----
    {
        const int g  = lane >> 2;
        const int t2 = (lane & 3) * 2;
        for (int b = 0; b < nblk; ++b) {
            #pragma unroll
            for (int j = 0; j < 2; ++j) {
                const int n = blkid[b] * 16 + j * 8 + t2;
                const float b0 = bs[n], b1 = bs[n + 1];
                #pragma unroll
                for (int i = 0; i < 2; ++i) {
                    const int m = p0 + wm * 32 + i * 16 + g;
                    *(float2*)&g_w_buf[(size_t)m * 144 + n] =
                        make_float2(acc2[b][i][j][0] + b0, acc2[b][i][j][1] + b1);
                    *(float2*)&g_w_buf[(size_t)(m + 8) * 144 + n] =
                        make_float2(acc2[b][i][j][2] + b0, acc2[b][i][j][3] + b1);
                }
            }
        }
    }
}

// ---------------- kernel: involution gather/reduce (proven) ----------------
#define INV_SMEM_FLOATS (3*18*256 + 16*144)

__global__ void __launch_bounds__(256)
k_inv(float* __restrict__ out)
{
    extern __shared__ float sm2[];
    float* xis = sm2;                       // [54][256]
    float* wsm = sm2 + 13824;               // [16][144]
    const uint32_t sb = smem_to_u32(sm2);

    const int t   = threadIdx.x;
    const int seg = blockIdx.x & 7;
    const int h   = (blockIdx.x >> 3) & 127;
    const int b   = blockIdx.x >> 10;
    const int w0  = seg * 16;
    const size_t prow = ((size_t)b * 128 + h) * 128;

    {
        const uint4* src = (const uint4*)(g_w_buf + (prow + w0) * 144);
        for (int i = t; i < 576; i += 256)
            cp_async16(sb + 55296 + i * 16, src + i);
    }
    for (int i = t; i < 3456; i += 256) {
        int pos = i >> 6, c4 = i & 63;
        int rr = pos / 18, cc = pos - rr * 18;
        int hhp = h - 1 + rr, wwp = w0 - 1 + cc;
        bool ok = ((unsigned)hhp < 128u) && ((unsigned)wwp < 128u);
        const uint4* s = ok
            ? (const uint4*)(g_xi_buf + (((size_t)b * 128 + hhp) * 128 + wwp) * 256) + c4
            : (const uint4*)g_xi_buf;
        cp_async16_z(sb + (uint32_t)(pos * 1024 + c4 * 16), s, ok ? 16 : 0);
    }
    CP_COMMIT();
    CP_WAIT(0);
    __syncthreads();

    const int o  = t;
    const int g  = o >> 4;
    const int fb = g * 144 + (o & 15) * 9;
    int off[9];
    #pragma unroll
    for (int kk = 0; kk < 9; kk++) {
        int flat = fb + kk;
        int kpos = flat >> 8;
        int c    = flat & 255;
        int di   = kpos / 3, dj = kpos - di * 3;
        off[kk]  = (di * 18 + dj) * 256 + c;
    }

    for (int px = 0; px < 16; px++) {
        const float* wp = &wsm[px * 144 + g * 9];
        const float* xb = &xis[px * 256];
        float acc = 0.f;
        #pragma unroll
        for (int kk = 0; kk < 9; kk++)
            acc = fmaf(wp[kk], xb[off[kk]], acc);
        out[(prow + w0 + px) * 256 + o] = acc;
    }
}

// ---------------- launch ----------------
extern "C" void kernel_launch(void* const* d_in, const int* in_sizes, int n_in,
                              void* d_out, int out_size)
{
    const float* x     = (const float*)d_in[0];
    const float* Wr    = (const float*)d_in[1];
    const float* br    = (const float*)d_in[2];
    const float* gamma = (const float*)d_in[3];
    const float* beta  = (const float*)d_in[4];
    const float* mean  = (const float*)d_in[5];
    const float* var   = (const float*)d_in[6];
    const float* Ws    = (const float*)d_in[7];
    const float* bs    = (const float*)d_in[8];
    const float* Wi    = (const float*)d_in[9];
    const float* bi    = (const float*)d_in[10];
    float* out = (float*)d_out;
    (void)in_sizes; (void)n_in; (void)out_size;

    const int smemX  = XG_SMEM;                                 // 196,608
    const int smemRW = RW_SMEM;                                 // 184,832
    const int smem2  = INV_SMEM_FLOATS * (int)sizeof(float);    // 64,512
    cudaFuncSetAttribute(k_xi_mma, cudaFuncAttributeMaxDynamicSharedMemorySize, smemX);
    cudaFuncSetAttribute(k_rw_mma, cudaFuncAttributeMaxDynamicSharedMemorySize, smemRW);
    cudaFuncSetAttribute(k_inv,    cudaFuncAttributeMaxDynamicSharedMemorySize, smem2);

    k_prepw  <<<22,         256>>>(Wi, Wr, Ws);
    k_xi_mma <<<NPIX / 128, 512, smemX>>>(x, bi);
    k_rw_mma <<<NPIX / 64,  256, smemRW>>>(x, br, gamma, beta, mean, var, bs);
    k_inv    <<<NPIX / 16,  256, smem2>>>(out);
}

// round 10
// speedup vs baseline: 1.0124x; 1.0124x over previous
#include <cuda_runtime.h>
#include <cuda_bf16.h>
#include <cstdint>

// Involution2D on GB300 — round 10: exact round-7 pipeline (201.4us known-good:
// prep_all + xi M=64 cp.async + rw full-prefetch) with ONE change: k_inv
// retiled 1x16 -> 4x16 px/CTA (halo amp 3.4x -> 1.69x; it is L1-wavefront
// bound at 76%).

#define BB   4
#define HH_  128
#define WW_  128
#define CC   256
#define CR   64
#define KKG  144
#define FF   256
#define NPIX (BB*HH_*WW_)   // 65536

__device__ __align__(16) float g_w_buf[(size_t)NPIX * KKG];
__device__ __align__(16) float g_xi_buf[(size_t)NPIX * FF];
__device__ __align__(16) unsigned int g_wiT_hi[256 * 128];       // [f][c/2]
__device__ __align__(16) unsigned int g_wiT_lo[256 * 128];
__device__ __align__(16) unsigned int g_wrT_hi[64 * 128];        // [n][c/2]
__device__ __align__(16) unsigned int g_wrT_lo[64 * 128];
__device__ __align__(16) unsigned int g_wsT_hi[144 * 32];        // [f][k/2]
__device__ __align__(16) unsigned int g_wsT_lo[144 * 32];
__device__ __align__(16) unsigned int g_x_hi[(size_t)NPIX * 128]; // [px][c/2]
__device__ __align__(16) unsigned int g_x_lo[(size_t)NPIX * 128];

#define SW(o) ((o) ^ (((o) >> 3) & 0x70))

__device__ __forceinline__ uint32_t smem_to_u32(const void* p) {
    uint32_t a;
    asm("{ .reg .u64 t; cvta.to.shared.u64 t, %1; cvt.u32.u64 %0, t; }"
        : "=r"(a) : "l"(p));
    return a;
}
__device__ __forceinline__ uint32_t bf16x2_rn(float lo, float hi) {
    uint32_t r;
    asm("cvt.rn.bf16x2.f32 %0, %1, %2;" : "=r"(r) : "f"(hi), "f"(lo));
    return r;
}
__device__ __forceinline__ void split2(float a, float b, uint32_t &hi, uint32_t &lo) {
    uint32_t ua = __float_as_uint(a), ub = __float_as_uint(b);
    hi = __byte_perm(ua, ub, 0x7632);
    lo = bf16x2_rn(a - __uint_as_float(ua & 0xFFFF0000u),
                   b - __uint_as_float(ub & 0xFFFF0000u));
}
__device__ __forceinline__ void cp_async16(uint32_t dst, const void* src) {
    asm volatile("{ .reg .u64 g; cvta.to.global.u64 g, %1;\n\t"
                 "cp.async.cg.shared.global [%0], [g], 16; }"
                 :: "r"(dst), "l"(src) : "memory");
}
__device__ __forceinline__ void cp_async16_z(uint32_t dst, const void* src, int sz) {
    asm volatile("{ .reg .u64 g; cvta.to.global.u64 g, %1;\n\t"
                 "cp.async.cg.shared.global [%0], [g], 16, %2; }"
                 :: "r"(dst), "l"(src), "r"(sz) : "memory");
}
#define CP_COMMIT() asm volatile("cp.async.commit_group;" ::: "memory")
#define CP_WAIT(n)  asm volatile("cp.async.wait_group %0;" :: "n"(n) : "memory")

__device__ __forceinline__ void ldsm4(uint32_t (&r)[4], const void* p) {
    uint32_t addr;
    asm("{ .reg .u64 t; cvta.to.shared.u64 t, %1; cvt.u32.u64 %0, t; }"
        : "=r"(addr) : "l"(p));
    asm volatile("ldmatrix.sync.aligned.m8n8.x4.shared.b16 {%0,%1,%2,%3}, [%4];"
                 : "=r"(r[0]), "=r"(r[1]), "=r"(r[2]), "=r"(r[3]) : "r"(addr));
}
__device__ __forceinline__ void mma16816(float (&d)[4], const uint32_t (&a)[4],
                                         uint32_t b0, uint32_t b1) {
    asm volatile(
        "mma.sync.aligned.m16n8k16.row.col.f32.bf16.bf16.f32 "
        "{%0,%1,%2,%3}, {%4,%5,%6,%7}, {%8,%9}, {%0,%1,%2,%3};"
        : "+f"(d[0]), "+f"(d[1]), "+f"(d[2]), "+f"(d[3])
        : "r"(a[0]), "r"(a[1]), "r"(a[2]), "r"(a[3]), "r"(b0), "r"(b1));
}

// ---------------- prep (single launch, all blocks concurrent) ----------------
__global__ void __launch_bounds__(256)
k_prep_all(const float* __restrict__ x,  const float* __restrict__ Wi,
           const float* __restrict__ Wr, const float* __restrict__ Ws)
{
    const int bid = blockIdx.x;
    const int t   = threadIdx.x;
    if (bid < 1024) {
        const int gid = bid * 256 + t;
        const float4* xs = (const float4*)x;
        #pragma unroll 4
        for (int i = gid; i < NPIX * 64; i += 262144) {
            float4 v = xs[i];
            uint32_t h0, l0, h1, l1;
            split2(v.x, v.y, h0, l0);
            split2(v.z, v.w, h1, l1);
            ((uint2*)g_x_hi)[i] = make_uint2(h0, h1);
            ((uint2*)g_x_lo)[i] = make_uint2(l0, l1);
        }
    } else if (bid < 1040) {
        const int idx = (bid - 1024) * 256 + t;
        for (int i = idx; i < 32768; i += 4096) {
            int f = i >> 7, cp = i & 127;
            uint32_t hi, lo;
            split2(Wi[(size_t)(2 * cp) * 256 + f],
                   Wi[(size_t)(2 * cp + 1) * 256 + f], hi, lo);
            g_wiT_hi[f * 128 + cp] = hi;
            g_wiT_lo[f * 128 + cp] = lo;
        }
    } else if (bid < 1044) {
        const int idx = (bid - 1040) * 256 + t;
        for (int i = idx; i < 8192; i += 1024) {
            int n = i >> 7, kp = i & 127;
            uint32_t hi, lo;
            split2(Wr[(2 * kp) * 64 + n], Wr[(2 * kp + 1) * 64 + n], hi, lo);
            g_wrT_hi[n * 128 + kp] = hi;
            g_wrT_lo[n * 128 + kp] = lo;
        }
    } else {
        const int idx = (bid - 1044) * 256 + t;
        for (int i = idx; i < 4608; i += 512) {
            int f = i >> 5, kp = i & 31;
            uint32_t hi, lo;
            split2(Ws[(2 * kp) * 144 + f], Ws[(2 * kp + 1) * 144 + f], hi, lo);
            g_wsT_hi[f * 32 + kp] = hi;
            g_wsT_lo[f * 32 + kp] = lo;
        }
    }
}

// ---------------- kernel: xi = x @ Wi + bi, 2-stage cp.async (round-7) ----------------
#define XG_A_HI 0
#define XG_A_LO 8192
#define XG_B_HI 16384
#define XG_B_LO 49152
#define XG_BUF  81920
#define XG_SMEM (2 * XG_BUF)   // 163840

__device__ __forceinline__ void xi_issue_chunk(uint32_t sb, int buf, int kb,
                                               int p0, int t)
{
    const uint32_t base = sb + buf * XG_BUF;
    const uint4* gxh = (const uint4*)g_x_hi;
    const uint4* gxl = (const uint4*)g_x_lo;
    const uint4* gbh = (const uint4*)g_wiT_hi;
    const uint4* gbl = (const uint4*)g_wiT_lo;
    #pragma unroll
    for (int it = 0; it < 2; ++it) {          // A: 64 rows x 8 x 16B
        int gi = t + it * 256;
        int row = gi >> 3, c = gi & 7;
        int src = (p0 + row) * 32 + kb * 8 + c;
        uint32_t d = SW(row * 128 + c * 16);
        cp_async16(base + XG_A_HI + d, gxh + src);
        cp_async16(base + XG_A_LO + d, gxl + src);
    }
    #pragma unroll
    for (int it = 0; it < 8; ++it) {          // B: 256 rows x 8 x 16B
        int gi = t + it * 256;
        int f = gi >> 3, c = gi & 7;
        int src = f * 32 + kb * 8 + c;
        uint32_t d = SW(f * 128 + c * 16);
        cp_async16(base + XG_B_HI + d, gbh + src);
        cp_async16(base + XG_B_LO + d, gbl + src);
    }
}

__global__ void __launch_bounds__(256, 1)
k_xi_mma(const float* __restrict__ bi)
{
    extern __shared__ char smc[];
    const uint32_t sb = smem_to_u32(smc);
    const int t    = threadIdx.x;
    const int wid  = t >> 5;
    const int lane = t & 31;
    const int p0   = blockIdx.x * 64;
    const int wm   = wid >> 2;
    const int wn   = wid & 3;

    float acc[2][8][4];
    #pragma unroll
    for (int i = 0; i < 2; ++i)
        #pragma unroll
        for (int j = 0; j < 8; ++j)
            #pragma unroll
            for (int q = 0; q < 4; ++q) acc[i][j][q] = 0.f;

    xi_issue_chunk(sb, 0, 0, p0, t); CP_COMMIT();
    xi_issue_chunk(sb, 1, 1, p0, t); CP_COMMIT();

    const int lr   = lane & 15;
    const int lk   = (lane >> 4) * 16;
    const int arow = wm * 32 + lr;
    const int brow = wn * 64 + lr;

    for (int kb = 0; kb < 4; ++kb) {
        if (kb < 3) CP_WAIT(1); else CP_WAIT(0);
        __syncthreads();
        char* base = smc + (kb & 1) * XG_BUF;
        #pragma unroll
        for (int k16 = 0; k16 < 4; ++k16) {
            const int ko = k16 * 32 + lk;
            uint32_t ah[2][4], al[2][4];
            #pragma unroll
            for (int i = 0; i < 2; ++i) {
                ldsm4(ah[i], base + XG_A_HI + SW((arow + i * 16) * 128 + ko));
                ldsm4(al[i], base + XG_A_LO + SW((arow + i * 16) * 128 + ko));
            }
            #pragma unroll
            for (int j = 0; j < 4; ++j) {
                uint32_t bh[4], bl[4];
                ldsm4(bh, base + XG_B_HI + SW((brow + j * 16) * 128 + ko));
                ldsm4(bl, base + XG_B_LO + SW((brow + j * 16) * 128 + ko));
                #pragma unroll
                for (int i = 0; i < 2; ++i) {
                    mma16816(acc[i][2*j],   ah[i], bh[0], bh[2]);
                    mma16816(acc[i][2*j+1], ah[i], bh[1], bh[3]);
                    mma16816(acc[i][2*j],   al[i], bh[0], bh[2]);
                    mma16816(acc[i][2*j+1], al[i], bh[1], bh[3]);
                    mma16816(acc[i][2*j],   ah[i], bl[0], bl[2]);
                    mma16816(acc[i][2*j+1], ah[i], bl[1], bl[3]);
                }
            }
        }
        __syncthreads();
        if (kb + 2 < 4) { xi_issue_chunk(sb, kb & 1, kb + 2, p0, t); CP_COMMIT(); }
    }

    const int g  = lane >> 2;
    const int t2 = (lane & 3) * 2;
    #pragma unroll
    for (int i = 0; i < 2; ++i) {
        const int m = p0 + wm * 32 + i * 16 + g;
        #pragma unroll
        for (int j = 0; j < 8; ++j) {
            const int n = wn * 64 + j * 8 + t2;
            float b0 = bi[n], b1 = bi[n + 1];
            *(float2*)&g_xi_buf[(size_t)m * 256 + n] =
                make_float2(acc[i][j][0] + b0, acc[i][j][1] + b1);
            *(float2*)&g_xi_buf[(size_t)(m + 8) * 256 + n] =
                make_float2(acc[i][j][2] + b0, acc[i][j][3] + b1);
        }
    }
}

// ---------------- kernel: r+w fused, full cp.async prefetch (round-7) ----------------
#define RW_WS_HI 0
#define RW_WS_LO 18432
#define RW_SC    36864
#define RW_SH    37120
#define RW_A_HI  37376     // 4 chunks x 8192
#define RW_A_LO  70144
#define RW_B_HI  102912
#define RW_B_LO  135680
#define RW_R_HI  168448
#define RW_R_LO  176640
#define RW_SMEM  184832

__global__ void __launch_bounds__(256, 1)
k_rw_mma(const float* __restrict__ br,   const float* __restrict__ gamma,
         const float* __restrict__ beta, const float* __restrict__ mean,
         const float* __restrict__ var,  const float* __restrict__ bs)
{
    extern __shared__ char smc[];
    const uint32_t sb = smem_to_u32(smc);
    const int t    = threadIdx.x;
    const int wid  = t >> 5;
    const int lane = t & 31;
    const int p0   = blockIdx.x * 64;
    const int wm   = wid >> 2;
    const int wn   = wid & 3;

    {
        const uint4* sh = (const uint4*)g_wsT_hi;
        const uint4* sl = (const uint4*)g_wsT_lo;
        for (int i = t; i < 1152; i += 256) {
            int f = i >> 3, c = i & 7;
            uint32_t d = SW(f * 128 + c * 16);
            cp_async16(sb + RW_WS_HI + d, sh + i);
            cp_async16(sb + RW_WS_LO + d, sl + i);
        }
    }
    CP_COMMIT();
    {
        const uint4* gxh = (const uint4*)g_x_hi;
        const uint4* gxl = (const uint4*)g_x_lo;
        const uint4* grh = (const uint4*)g_wrT_hi;
        const uint4* grl = (const uint4*)g_wrT_lo;
        #pragma unroll
        for (int kb = 0; kb < 4; ++kb) {
            #pragma unroll
            for (int it = 0; it < 2; ++it) {
                int gi = t + it * 256;
                int row = gi >> 3, c = gi & 7;
                int src = (p0 + row) * 32 + kb * 8 + c;
                uint32_t d = kb * 8192 + SW(row * 128 + c * 16);
                cp_async16(sb + RW_A_HI + d, gxh + src);
                cp_async16(sb + RW_A_LO + d, gxl + src);
            }
            #pragma unroll
            for (int it = 0; it < 2; ++it) {
                int gi = t + it * 256;
                int n = gi >> 3, c = gi & 7;
                int src = n * 32 + kb * 8 + c;
                uint32_t d = kb * 8192 + SW(n * 128 + c * 16);
                cp_async16(sb + RW_B_HI + d, grh + src);
                cp_async16(sb + RW_B_LO + d, grl + src);
            }
            CP_COMMIT();
        }
    }
    if (t < 64) {
        float s = gamma[t] * rsqrtf(var[t] + 1e-3f);
        *(float*)(smc + RW_SC + t * 4) = s;
        *(float*)(smc + RW_SH + t * 4) = (br[t] - mean[t]) * s + beta[t];
    }

    const int lr    = lane & 15;
    const int lk    = (lane >> 4) * 16;
    const int arow  = wm * 32 + lr;
    const int brow1 = wn * 16 + lr;

    float acc1[2][2][4];
    #pragma unroll
    for (int i = 0; i < 2; ++i)
        #pragma unroll
        for (int j = 0; j < 2; ++j)
            #pragma unroll
            for (int q = 0; q < 4; ++q) acc1[i][j][q] = 0.f;

    #pragma unroll
    for (int kb = 0; kb < 4; ++kb) {
        if      (kb == 0) CP_WAIT(3);
        else if (kb == 1) CP_WAIT(2);
        else if (kb == 2) CP_WAIT(1);
        else              CP_WAIT(0);
        __syncthreads();
        char* abase  = smc + RW_A_HI + kb * 8192;
        char* albase = smc + RW_A_LO + kb * 8192;
        char* bbase  = smc + RW_B_HI + kb * 8192;
        char* blbase = smc + RW_B_LO + kb * 8192;
        #pragma unroll
        for (int k16 = 0; k16 < 4; ++k16) {
            const int ko = k16 * 32 + lk;
            uint32_t ah[2][4], al[2][4], bh[4], bl[4];
            #pragma unroll
            for (int i = 0; i < 2; ++i) {
                ldsm4(ah[i], abase  + SW((arow + i * 16) * 128 + ko));
                ldsm4(al[i], albase + SW((arow + i * 16) * 128 + ko));
            }
            ldsm4(bh, bbase  + SW(brow1 * 128 + ko));
            ldsm4(bl, blbase + SW(brow1 * 128 + ko));
            #pragma unroll
            for (int i = 0; i < 2; ++i) {
                mma16816(acc1[i][0], ah[i], bh[0], bh[2]);
                mma16816(acc1[i][1], ah[i], bh[1], bh[3]);
                mma16816(acc1[i][0], al[i], bh[0], bh[2]);
                mma16816(acc1[i][1], al[i], bh[1], bh[3]);
                mma16816(acc1[i][0], ah[i], bl[0], bl[2]);
                mma16816(acc1[i][1], ah[i], bl[1], bl[3]);
            }
        }
    }

    {
        const int g  = lane >> 2;
        const int t2 = (lane & 3) * 2;
        #pragma unroll
        for (int i = 0; i < 2; ++i) {
            #pragma unroll
            for (int n8 = 0; n8 < 2; ++n8) {
                const int n0 = wn * 16 + n8 * 8 + t2;
                const float s0 = *(float*)(smc + RW_SC + n0 * 4);
                const float s1 = *(float*)(smc + RW_SC + (n0 + 1) * 4);
                const float h0 = *(float*)(smc + RW_SH + n0 * 4);
                const float h1 = *(float*)(smc + RW_SH + (n0 + 1) * 4);
                #pragma unroll
                for (int half = 0; half < 2; ++half) {
                    const int m = wm * 32 + i * 16 + g + half * 8;
                    float r0 = fmaxf(fmaf(acc1[i][n8][half * 2],     s0, h0), 0.f);
                    float r1 = fmaxf(fmaf(acc1[i][n8][half * 2 + 1], s1, h1), 0.f);
                    uint32_t hi, lo;
                    split2(r0, r1, hi, lo);
                    uint32_t d = SW(m * 128 + n0 * 2);
                    *(uint32_t*)(smc + RW_R_HI + d) = hi;
                    *(uint32_t*)(smc + RW_R_LO + d) = lo;
                }
            }
        }
    }
    __syncthreads();

    const int nblk = (wn == 3) ? 3 : 2;
    int blkid[3] = {wn, wn + 4, 8};
    float acc2[3][2][2][4];
    #pragma unroll
    for (int b = 0; b < 3; ++b)
        #pragma unroll
        for (int i = 0; i < 2; ++i)
            #pragma unroll
            for (int j = 0; j < 2; ++j)
                #pragma unroll
                for (int q = 0; q < 4; ++q) acc2[b][i][j][q] = 0.f;

    #pragma unroll
    for (int k16 = 0; k16 < 4; ++k16) {
        const int ko = k16 * 32 + lk;
        uint32_t ah[2][4], al[2][4];
        #pragma unroll
        for (int i = 0; i < 2; ++i) {
            ldsm4(ah[i], smc + RW_R_HI + SW((arow + i * 16) * 128 + ko));
            ldsm4(al[i], smc + RW_R_LO + SW((arow + i * 16) * 128 + ko));
        }
        for (int b = 0; b < nblk; ++b) {
            const int brow = blkid[b] * 16 + lr;
            uint32_t bh[4], bl[4];
            ldsm4(bh, smc + RW_WS_HI + SW(brow * 128 + ko));
            ldsm4(bl, smc + RW_WS_LO + SW(brow * 128 + ko));
            #pragma unroll
            for (int i = 0; i < 2; ++i) {
                mma16816(acc2[b][i][0], ah[i], bh[0], bh[2]);
                mma16816(acc2[b][i][1], ah[i], bh[1], bh[3]);
                mma16816(acc2[b][i][0], al[i], bh[0], bh[2]);
                mma16816(acc2[b][i][1], al[i], bh[1], bh[3]);
                mma16816(acc2[b][i][0], ah[i], bl[0], bl[2]);
                mma16816(acc2[b][i][1], ah[i], bl[1], bl[3]);
            }
        }
    }

    {
        const int g  = lane >> 2;
        const int t2 = (lane & 3) * 2;
        for (int b = 0; b < nblk; ++b) {
            #pragma unroll
            for (int j = 0; j < 2; ++j) {
                const int n = blkid[b] * 16 + j * 8 + t2;
                const float b0 = bs[n], b1 = bs[n + 1];
                #pragma unroll
                for (int i = 0; i < 2; ++i) {
                    const int m = p0 + wm * 32 + i * 16 + g;
                    *(float2*)&g_w_buf[(size_t)m * 144 + n] =
                        make_float2(acc2[b][i][j][0] + b0, acc2[b][i][j][1] + b1);
                    *(float2*)&g_w_buf[(size_t)(m + 8) * 144 + n] =
                        make_float2(acc2[b][i][j][2] + b0, acc2[b][i][j][3] + b1);
                }
            }
        }
    }
}

// ---------------- kernel: involution gather, 4x16 px/CTA ----------------
// smem: xi halo [6][18][256] = 110,592 B; w tile [64][144] = 36,864 B.
#define INV_W_OFF 110592
#define INV_SMEM  147456

__global__ void __launch_bounds__(512)
k_inv(float* __restrict__ out)
{
    extern __shared__ float sm2[];
    float* xis = sm2;                        // [108][256]
    float* wsm = sm2 + 27648;                // [64][144]
    const uint32_t sb = smem_to_u32(sm2);

    const int t    = threadIdx.x;
    const int seg  = blockIdx.x & 7;         // 8 col segments
    const int rg   = (blockIdx.x >> 3) & 31; // 32 row groups of 4
    const int b    = blockIdx.x >> 8;        // 4 batches
    const int w0   = seg * 16;
    const int h0   = rg * 4;

    // dynamic weights: 4 rows x 16 px x 144 floats (contiguous per row)
    for (int i = t; i < 2304; i += 512) {    // 2304 uint4 total
        int r = i / 576, j = i - r * 576;    // 576 uint4 per row
        const uint4* src = (const uint4*)(g_w_buf +
            (((size_t)b * 128 + h0 + r) * 128 + w0) * 144);
        cp_async16(sb + INV_W_OFF + (uint32_t)(r * 9216 + j * 16), src + j);
    }
    // xi halo: rows h0-1..h0+4, cols w0-1..w0+16, zfill OOB
    for (int i = t; i < 6912; i += 512) {
        int pos = i >> 6, c4 = i & 63;       // 108 positions x 64 granules
        int rr = pos / 18, cc = pos - rr * 18;
        int hhp = h0 - 1 + rr, wwp = w0 - 1 + cc;
        bool ok = ((unsigned)hhp < 128u) && ((unsigned)wwp < 128u);
        const uint4* s = ok
            ? (const uint4*)(g_xi_buf + (((size_t)b * 128 + hhp) * 128 + wwp) * 256) + c4
            : (const uint4*)g_xi_buf;
        cp_async16_z(sb + (uint32_t)(pos * 1024 + c4 * 16), s, ok ? 16 : 0);
    }
    CP_COMMIT();
    CP_WAIT(0);
    __syncthreads();

    const int o  = t & 255;                  // output channel
    const int ph = t >> 8;                   // pixel half: 0 or 1
    const int g  = o >> 4;
    const int fb = g * 144 + (o & 15) * 9;
    int off[9];
    #pragma unroll
    for (int kk = 0; kk < 9; kk++) {
        int flat = fb + kk;
        int kpos = flat >> 8;
        int c    = flat & 255;
        int di   = kpos / 3, dj = kpos - di * 3;
        off[kk]  = (di * 18 + dj) * 256 + c;
    }

    #pragma unroll 4
    for (int px = 0; px < 32; px++) {
        const int pid = ph * 32 + px;        // 0..63 tile-local pixel
        const int r  = pid >> 4, cc = pid & 15;
        const float* wp = &wsm[pid * 144 + g * 9];
        const float* xb = &xis[(r * 18 + cc) * 256];
        float acc = 0.f;
        #pragma unroll
        for (int kk = 0; kk < 9; kk++)
            acc = fmaf(wp[kk], xb[off[kk]], acc);
        out[(((size_t)b * 128 + h0 + r) * 128 + w0 + cc) * 256 + o] = acc;
    }
}

// ---------------- launch ----------------
extern "C" void kernel_launch(void* const* d_in, const int* in_sizes, int n_in,
                              void* d_out, int out_size)
{
    const float* x     = (const float*)d_in[0];
    const float* Wr    = (const float*)d_in[1];
    const float* br    = (const float*)d_in[2];
    const float* gamma = (const float*)d_in[3];
    const float* beta  = (const float*)d_in[4];
    const float* mean  = (const float*)d_in[5];
    const float* var   = (const float*)d_in[6];
    const float* Ws    = (const float*)d_in[7];
    const float* bs    = (const float*)d_in[8];
    const float* Wi    = (const float*)d_in[9];
    const float* bi    = (const float*)d_in[10];
    float* out = (float*)d_out;
    (void)in_sizes; (void)n_in; (void)out_size;

    const int smemX  = XG_SMEM;    // 163,840
    const int smemRW = RW_SMEM;    // 184,832
    const int smem2  = INV_SMEM;   // 147,456
    cudaFuncSetAttribute(k_xi_mma, cudaFuncAttributeMaxDynamicSharedMemorySize, smemX);
    cudaFuncSetAttribute(k_rw_mma, cudaFuncAttributeMaxDynamicSharedMemorySize, smemRW);
    cudaFuncSetAttribute(k_inv,    cudaFuncAttributeMaxDynamicSharedMemorySize, smem2);

    k_prep_all<<<1046,      256>>>(x, Wi, Wr, Ws);
    k_xi_mma  <<<NPIX / 64, 256, smemX>>>(bi);
    k_rw_mma  <<<NPIX / 64, 256, smemRW>>>(br, gamma, beta, mean, var, bs);
    k_inv     <<<1024,      512, smem2>>>(out);
}

// round 11
// speedup vs baseline: 1.1449x; 1.1309x over previous
#include <cuda_runtime.h>
#include <cuda_bf16.h>
#include <cstdint>

// Involution2D on GB300 — round 11:
//   k_prep_all : x split + weight transposes (round-7 proven)
//   k_fused    : xi = x@Wi + bi  AND  r=relu(BN(x@Wr)), w=r@Ws+bs in ONE
//                kernel — A (x hi/lo) streamed once, GEMM1 piggybacks on the
//                same ldsm fragments; Ws/r reuse dead buffer space post-loop.
//   k_inv      : round-7 16px version (4x16 retile regressed; reverted)

#define BB   4
#define HH_  128
#define WW_  128
#define CC   256
#define CR   64
#define KKG  144
#define FF   256
#define NPIX (BB*HH_*WW_)   // 65536

__device__ __align__(16) float g_w_buf[(size_t)NPIX * KKG];
__device__ __align__(16) float g_xi_buf[(size_t)NPIX * FF];
__device__ __align__(16) unsigned int g_wiT_hi[256 * 128];       // [f][c/2]
__device__ __align__(16) unsigned int g_wiT_lo[256 * 128];
__device__ __align__(16) unsigned int g_wrT_hi[64 * 128];        // [n][c/2]
__device__ __align__(16) unsigned int g_wrT_lo[64 * 128];
__device__ __align__(16) unsigned int g_wsT_hi[144 * 32];        // [f][k/2]
__device__ __align__(16) unsigned int g_wsT_lo[144 * 32];
__device__ __align__(16) unsigned int g_x_hi[(size_t)NPIX * 128]; // [px][c/2]
__device__ __align__(16) unsigned int g_x_lo[(size_t)NPIX * 128];

#define SW(o) ((o) ^ (((o) >> 3) & 0x70))

__device__ __forceinline__ uint32_t smem_to_u32(const void* p) {
    uint32_t a;
    asm("{ .reg .u64 t; cvta.to.shared.u64 t, %1; cvt.u32.u64 %0, t; }"
        : "=r"(a) : "l"(p));
    return a;
}
__device__ __forceinline__ uint32_t bf16x2_rn(float lo, float hi) {
    uint32_t r;
    asm("cvt.rn.bf16x2.f32 %0, %1, %2;" : "=r"(r) : "f"(hi), "f"(lo));
    return r;
}
__device__ __forceinline__ void split2(float a, float b, uint32_t &hi, uint32_t &lo) {
    uint32_t ua = __float_as_uint(a), ub = __float_as_uint(b);
    hi = __byte_perm(ua, ub, 0x7632);
    lo = bf16x2_rn(a - __uint_as_float(ua & 0xFFFF0000u),
                   b - __uint_as_float(ub & 0xFFFF0000u));
}
__device__ __forceinline__ void cp_async16(uint32_t dst, const void* src) {
    asm volatile("{ .reg .u64 g; cvta.to.global.u64 g, %1;\n\t"
                 "cp.async.cg.shared.global [%0], [g], 16; }"
                 :: "r"(dst), "l"(src) : "memory");
}
__device__ __forceinline__ void cp_async16_z(uint32_t dst, const void* src, int sz) {
    asm volatile("{ .reg .u64 g; cvta.to.global.u64 g, %1;\n\t"
                 "cp.async.cg.shared.global [%0], [g], 16, %2; }"
                 :: "r"(dst), "l"(src), "r"(sz) : "memory");
}
#define CP_COMMIT() asm volatile("cp.async.commit_group;" ::: "memory")
#define CP_WAIT(n)  asm volatile("cp.async.wait_group %0;" :: "n"(n) : "memory")

__device__ __forceinline__ void ldsm4(uint32_t (&r)[4], const void* p) {
    uint32_t addr;
    asm("{ .reg .u64 t; cvta.to.shared.u64 t, %1; cvt.u32.u64 %0, t; }"
        : "=r"(addr) : "l"(p));
    asm volatile("ldmatrix.sync.aligned.m8n8.x4.shared.b16 {%0,%1,%2,%3}, [%4];"
                 : "=r"(r[0]), "=r"(r[1]), "=r"(r[2]), "=r"(r[3]) : "r"(addr));
}
__device__ __forceinline__ void mma16816(float (&d)[4], const uint32_t (&a)[4],
                                         uint32_t b0, uint32_t b1) {
    asm volatile(
        "mma.sync.aligned.m16n8k16.row.col.f32.bf16.bf16.f32 "
        "{%0,%1,%2,%3}, {%4,%5,%6,%7}, {%8,%9}, {%0,%1,%2,%3};"
        : "+f"(d[0]), "+f"(d[1]), "+f"(d[2]), "+f"(d[3])
        : "r"(a[0]), "r"(a[1]), "r"(a[2]), "r"(a[3]), "r"(b0), "r"(b1));
}

// ---------------- prep (single launch, round-7 proven) ----------------
__global__ void __launch_bounds__(256)
k_prep_all(const float* __restrict__ x,  const float* __restrict__ Wi,
           const float* __restrict__ Wr, const float* __restrict__ Ws)
{
    const int bid = blockIdx.x;
    const int t   = threadIdx.x;
    if (bid < 1024) {
        const int gid = bid * 256 + t;
        const float4* xs = (const float4*)x;
        #pragma unroll 4
        for (int i = gid; i < NPIX * 64; i += 262144) {
            float4 v = xs[i];
            uint32_t h0, l0, h1, l1;
            split2(v.x, v.y, h0, l0);
            split2(v.z, v.w, h1, l1);
            ((uint2*)g_x_hi)[i] = make_uint2(h0, h1);
            ((uint2*)g_x_lo)[i] = make_uint2(l0, l1);
        }
    } else if (bid < 1040) {
        const int idx = (bid - 1024) * 256 + t;
        for (int i = idx; i < 32768; i += 4096) {
            int f = i >> 7, cp = i & 127;
            uint32_t hi, lo;
            split2(Wi[(size_t)(2 * cp) * 256 + f],
                   Wi[(size_t)(2 * cp + 1) * 256 + f], hi, lo);
            g_wiT_hi[f * 128 + cp] = hi;
            g_wiT_lo[f * 128 + cp] = lo;
        }
    } else if (bid < 1044) {
        const int idx = (bid - 1040) * 256 + t;
        for (int i = idx; i < 8192; i += 1024) {
            int n = i >> 7, kp = i & 127;
            uint32_t hi, lo;
            split2(Wr[(2 * kp) * 64 + n], Wr[(2 * kp + 1) * 64 + n], hi, lo);
            g_wrT_hi[n * 128 + kp] = hi;
            g_wrT_lo[n * 128 + kp] = lo;
        }
    } else {
        const int idx = (bid - 1044) * 256 + t;
        for (int i = idx; i < 4608; i += 512) {
            int f = i >> 5, kp = i & 31;
            uint32_t hi, lo;
            split2(Ws[(2 * kp) * 144 + f], Ws[(2 * kp + 1) * 144 + f], hi, lo);
            g_wsT_hi[f * 32 + kp] = hi;
            g_wsT_lo[f * 32 + kp] = lo;
        }
    }
}

// ---------------- fused kernel: xi AND r/w, A streamed once ----------------
// Per-buffer layout (96 KB x 2):
//   A_HI 8K | A_LO 8K | BWI_HI 32K | BWI_LO 32K | BWR_HI 8K | BWR_LO 8K
// Post-mainloop regions reuse buffer-0 space:
//   WS_HI 18K | WS_LO 18K | SC 256 | SH 256 | R_HI 8K | R_LO 8K
#define FX_A_HI   0
#define FX_A_LO   8192
#define FX_BI_HI  16384
#define FX_BI_LO  49152
#define FX_BR_HI  81920
#define FX_BR_LO  90112
#define FX_BUF    98304
#define FX_SMEM   (2 * FX_BUF)   // 196608
#define FX_WS_HI  0
#define FX_WS_LO  18432
#define FX_SC     36864
#define FX_SH     37120
#define FX_R_HI   37376
#define FX_R_LO   45568

__device__ __forceinline__ void fx_issue_chunk(uint32_t sb, int buf, int kb,
                                               int p0, int t)
{
    const uint32_t base = sb + buf * FX_BUF;
    const uint4* gxh = (const uint4*)g_x_hi;
    const uint4* gxl = (const uint4*)g_x_lo;
    const uint4* gih = (const uint4*)g_wiT_hi;
    const uint4* gil = (const uint4*)g_wiT_lo;
    const uint4* grh = (const uint4*)g_wrT_hi;
    const uint4* grl = (const uint4*)g_wrT_lo;
    #pragma unroll
    for (int it = 0; it < 2; ++it) {          // A: 64 rows x 8 x 16B
        int gi = t + it * 256;
        int row = gi >> 3, c = gi & 7;
        int src = (p0 + row) * 32 + kb * 8 + c;
        uint32_t d = SW(row * 128 + c * 16);
        cp_async16(base + FX_A_HI + d, gxh + src);
        cp_async16(base + FX_A_LO + d, gxl + src);
    }
    #pragma unroll
    for (int it = 0; it < 8; ++it) {          // B_wi: 256 rows x 8 x 16B
        int gi = t + it * 256;
        int f = gi >> 3, c = gi & 7;
        int src = f * 32 + kb * 8 + c;
        uint32_t d = SW(f * 128 + c * 16);
        cp_async16(base + FX_BI_HI + d, gih + src);
        cp_async16(base + FX_BI_LO + d, gil + src);
    }
    #pragma unroll
    for (int it = 0; it < 2; ++it) {          // B_wr: 64 rows x 8 x 16B
        int gi = t + it * 256;
        int n = gi >> 3, c = gi & 7;
        int src = n * 32 + kb * 8 + c;
        uint32_t d = SW(n * 128 + c * 16);
        cp_async16(base + FX_BR_HI + d, grh + src);
        cp_async16(base + FX_BR_LO + d, grl + src);
    }
}

__global__ void __launch_bounds__(256, 1)
k_fused(const float* __restrict__ bi,
        const float* __restrict__ br,   const float* __restrict__ gamma,
        const float* __restrict__ beta, const float* __restrict__ mean,
        const float* __restrict__ var,  const float* __restrict__ bs)
{
    extern __shared__ char smc[];
    const uint32_t sb = smem_to_u32(smc);
    const int t    = threadIdx.x;
    const int wid  = t >> 5;
    const int lane = t & 31;
    const int p0   = blockIdx.x * 64;
    const int wm   = wid >> 2;
    const int wn   = wid & 3;

    float acc[2][8][4];     // xi accumulators
    float acc1[2][2][4];    // GEMM1 accumulators
    #pragma unroll
    for (int i = 0; i < 2; ++i) {
        #pragma unroll
        for (int j = 0; j < 8; ++j)
            #pragma unroll
            for (int q = 0; q < 4; ++q) acc[i][j][q] = 0.f;
        #pragma unroll
        for (int j = 0; j < 2; ++j)
            #pragma unroll
            for (int q = 0; q < 4; ++q) acc1[i][j][q] = 0.f;
    }

    fx_issue_chunk(sb, 0, 0, p0, t); CP_COMMIT();
    fx_issue_chunk(sb, 1, 1, p0, t); CP_COMMIT();

    const int lr    = lane & 15;
    const int lk    = (lane >> 4) * 16;
    const int arow  = wm * 32 + lr;
    const int brow  = wn * 64 + lr;     // xi B rows
    const int brow1 = wn * 16 + lr;     // GEMM1 B rows

    for (int kb = 0; kb < 4; ++kb) {
        if (kb < 3) CP_WAIT(1); else CP_WAIT(0);
        __syncthreads();
        char* base = smc + (kb & 1) * FX_BUF;
        #pragma unroll
        for (int k16 = 0; k16 < 4; ++k16) {
            const int ko = k16 * 32 + lk;
            uint32_t ah[2][4], al[2][4];
            #pragma unroll
            for (int i = 0; i < 2; ++i) {
                ldsm4(ah[i], base + FX_A_HI + SW((arow + i * 16) * 128 + ko));
                ldsm4(al[i], base + FX_A_LO + SW((arow + i * 16) * 128 + ko));
            }
            // GEMM1 (x @ Wr) on the same A fragments
            {
                uint32_t bh[4], bl[4];
                ldsm4(bh, base + FX_BR_HI + SW(brow1 * 128 + ko));
                ldsm4(bl, base + FX_BR_LO + SW(brow1 * 128 + ko));
                #pragma unroll
                for (int i = 0; i < 2; ++i) {
                    mma16816(acc1[i][0], ah[i], bh[0], bh[2]);
                    mma16816(acc1[i][1], ah[i], bh[1], bh[3]);
                    mma16816(acc1[i][0], al[i], bh[0], bh[2]);
                    mma16816(acc1[i][1], al[i], bh[1], bh[3]);
                    mma16816(acc1[i][0], ah[i], bl[0], bl[2]);
                    mma16816(acc1[i][1], ah[i], bl[1], bl[3]);
                }
            }
            // xi (x @ Wi)
            #pragma unroll
            for (int j = 0; j < 4; ++j) {
                uint32_t bh[4], bl[4];
                ldsm4(bh, base + FX_BI_HI + SW((brow + j * 16) * 128 + ko));
                ldsm4(bl, base + FX_BI_LO + SW((brow + j * 16) * 128 + ko));
                #pragma unroll
                for (int i = 0; i < 2; ++i) {
                    mma16816(acc[i][2*j],   ah[i], bh[0], bh[2]);
                    mma16816(acc[i][2*j+1], ah[i], bh[1], bh[3]);
                    mma16816(acc[i][2*j],   al[i], bh[0], bh[2]);
                    mma16816(acc[i][2*j+1], al[i], bh[1], bh[3]);
                    mma16816(acc[i][2*j],   ah[i], bl[0], bl[2]);
                    mma16816(acc[i][2*j+1], ah[i], bl[1], bl[3]);
                }
            }
        }
        __syncthreads();
        if (kb + 2 < 4) { fx_issue_chunk(sb, kb & 1, kb + 2, p0, t); CP_COMMIT(); }
    }
    // Mainloop done; buffers are dead. Issue WsT into buf0 space (latency
    // hides under the epilogues below).
    {
        const uint4* sh = (const uint4*)g_wsT_hi;
        const uint4* sl = (const uint4*)g_wsT_lo;
        for (int i = t; i < 1152; i += 256) {
            int f = i >> 3, c = i & 7;
            uint32_t d = SW(f * 128 + c * 16);
            cp_async16(sb + FX_WS_HI + d, sh + i);
            cp_async16(sb + FX_WS_LO + d, sl + i);
        }
        CP_COMMIT();
    }
    // BN constants
    if (t < 64) {
        float s = gamma[t] * rsqrtf(var[t] + 1e-3f);
        *(float*)(smc + FX_SC + t * 4) = s;
        *(float*)(smc + FX_SH + t * 4) = (br[t] - mean[t]) * s + beta[t];
    }
    __syncthreads();

    const int g  = lane >> 2;
    const int t2 = (lane & 3) * 2;

    // epilogue 1: BN + relu on acc1, split r -> smem hi/lo
    #pragma unroll
    for (int i = 0; i < 2; ++i) {
        #pragma unroll
        for (int n8 = 0; n8 < 2; ++n8) {
            const int n0 = wn * 16 + n8 * 8 + t2;
            const float s0 = *(float*)(smc + FX_SC + n0 * 4);
            const float s1 = *(float*)(smc + FX_SC + (n0 + 1) * 4);
            const float h0 = *(float*)(smc + FX_SH + n0 * 4);
            const float h1 = *(float*)(smc + FX_SH + (n0 + 1) * 4);
            #pragma unroll
            for (int half = 0; half < 2; ++half) {
                const int m = wm * 32 + i * 16 + g + half * 8;
                float r0 = fmaxf(fmaf(acc1[i][n8][half * 2],     s0, h0), 0.f);
                float r1 = fmaxf(fmaf(acc1[i][n8][half * 2 + 1], s1, h1), 0.f);
                uint32_t hi, lo;
                split2(r0, r1, hi, lo);
                uint32_t d = SW(m * 128 + n0 * 2);
                *(uint32_t*)(smc + FX_R_HI + d) = hi;
                *(uint32_t*)(smc + FX_R_LO + d) = lo;
            }
        }
    }

    // xi epilogue: acc -> g_xi_buf (+bi); global stores overlap Ws arrival
    #pragma unroll
    for (int i = 0; i < 2; ++i) {
        const int m = p0 + wm * 32 + i * 16 + g;
        #pragma unroll
        for (int j = 0; j < 8; ++j) {
            const int n = wn * 64 + j * 8 + t2;
            float b0 = bi[n], b1 = bi[n + 1];
            *(float2*)&g_xi_buf[(size_t)m * 256 + n] =
                make_float2(acc[i][j][0] + b0, acc[i][j][1] + b1);
            *(float2*)&g_xi_buf[(size_t)(m + 8) * 256 + n] =
                make_float2(acc[i][j][2] + b0, acc[i][j][3] + b1);
        }
    }

    CP_WAIT(0);
    __syncthreads();

    // GEMM2: w = r @ Ws + bs  (N=144, K=64)
    const int nblk = (wn == 3) ? 3 : 2;
    int blkid[3] = {wn, wn + 4, 8};
    float acc2[3][2][2][4];
    #pragma unroll
    for (int b = 0; b < 3; ++b)
        #pragma unroll
        for (int i = 0; i < 2; ++i)
            #pragma unroll
            for (int j = 0; j < 2; ++j)
                #pragma unroll
                for (int q = 0; q < 4; ++q) acc2[b][i][j][q] = 0.f;

    #pragma unroll
    for (int k16 = 0; k16 < 4; ++k16) {
        const int ko = k16 * 32 + lk;
        uint32_t ah[2][4], al[2][4];
        #pragma unroll
        for (int i = 0; i < 2; ++i) {
            ldsm4(ah[i], smc + FX_R_HI + SW((arow + i * 16) * 128 + ko));
            ldsm4(al[i], smc + FX_R_LO + SW((arow + i * 16) * 128 + ko));
        }
        for (int b = 0; b < nblk; ++b) {
            const int brw = blkid[b] * 16 + lr;
            uint32_t bh[4], bl[4];
            ldsm4(bh, smc + FX_WS_HI + SW(brw * 128 + ko));
            ldsm4(bl, smc + FX_WS_LO + SW(brw * 128 + ko));
            #pragma unroll
            for (int i = 0; i < 2; ++i) {
                mma16816(acc2[b][i][0], ah[i], bh[0], bh[2]);
                mma16816(acc2[b][i][1], ah[i], bh[1], bh[3]);
                mma16816(acc2[b][i][0], al[i], bh[0], bh[2]);
                mma16816(acc2[b][i][1], al[i], bh[1], bh[3]);
                mma16816(acc2[b][i][0], ah[i], bl[0], bl[2]);
                mma16816(acc2[b][i][1], ah[i], bl[1], bl[3]);
            }
        }
    }

    // epilogue 2: w -> g_w_buf (+bs)
    for (int b = 0; b < nblk; ++b) {
        #pragma unroll
        for (int j = 0; j < 2; ++j) {
            const int n = blkid[b] * 16 + j * 8 + t2;
            const float b0 = bs[n], b1 = bs[n + 1];
            #pragma unroll
            for (int i = 0; i < 2; ++i) {
                const int m = p0 + wm * 32 + i * 16 + g;
                *(float2*)&g_w_buf[(size_t)m * 144 + n] =
                    make_float2(acc2[b][i][j][0] + b0, acc2[b][i][j][1] + b1);
                *(float2*)&g_w_buf[(size_t)(m + 8) * 144 + n] =
                    make_float2(acc2[b][i][j][2] + b0, acc2[b][i][j][3] + b1);
            }
        }
    }
}

// ---------------- kernel: involution gather (round-7 proven, 16px/CTA) ----------------
#define INV_SMEM_FLOATS (3*18*256 + 16*144)

__global__ void __launch_bounds__(256)
k_inv(float* __restrict__ out)
{
    extern __shared__ float sm2[];
    float* xis = sm2;                       // [54][256]
    float* wsm = sm2 + 13824;               // [16][144]
    const uint32_t sb = smem_to_u32(sm2);

    const int t   = threadIdx.x;
    const int seg = blockIdx.x & 7;
    const int h   = (blockIdx.x >> 3) & 127;
    const int b   = blockIdx.x >> 10;
    const int w0  = seg * 16;
    const size_t prow = ((size_t)b * 128 + h) * 128;

    {
        const uint4* src = (const uint4*)(g_w_buf + (prow + w0) * 144);
        for (int i = t; i < 576; i += 256)
            cp_async16(sb + 55296 + i * 16, src + i);
    }
    for (int i = t; i < 3456; i += 256) {
        int pos = i >> 6, c4 = i & 63;
        int rr = pos / 18, cc = pos - rr * 18;
        int hhp = h - 1 + rr, wwp = w0 - 1 + cc;
        bool ok = ((unsigned)hhp < 128u) && ((unsigned)wwp < 128u);
        const uint4* s = ok
            ? (const uint4*)(g_xi_buf + (((size_t)b * 128 + hhp) * 128 + wwp) * 256) + c4
            : (const uint4*)g_xi_buf;
        cp_async16_z(sb + (uint32_t)(pos * 1024 + c4 * 16), s, ok ? 16 : 0);
    }
    CP_COMMIT();
    CP_WAIT(0);
    __syncthreads();

    const int o  = t;
    const int g  = o >> 4;
    const int fb = g * 144 + (o & 15) * 9;
    int off[9];
    #pragma unroll
    for (int kk = 0; kk < 9; kk++) {
        int flat = fb + kk;
        int kpos = flat >> 8;
        int c    = flat & 255;
        int di   = kpos / 3, dj = kpos - di * 3;
        off[kk]  = (di * 18 + dj) * 256 + c;
    }

    for (int px = 0; px < 16; px++) {
        const float* wp = &wsm[px * 144 + g * 9];
        const float* xb = &xis[px * 256];
        float acc = 0.f;
        #pragma unroll
        for (int kk = 0; kk < 9; kk++)
            acc = fmaf(wp[kk], xb[off[kk]], acc);
        out[(prow + w0 + px) * 256 + o] = acc;
    }
}

// ---------------- launch ----------------
extern "C" void kernel_launch(void* const* d_in, const int* in_sizes, int n_in,
                              void* d_out, int out_size)
{
    const float* x     = (const float*)d_in[0];
    const float* Wr    = (const float*)d_in[1];
    const float* br    = (const float*)d_in[2];
    const float* gamma = (const float*)d_in[3];
    const float* beta  = (const float*)d_in[4];
    const float* mean  = (const float*)d_in[5];
    const float* var   = (const float*)d_in[6];
    const float* Ws    = (const float*)d_in[7];
    const float* bs    = (const float*)d_in[8];
    const float* Wi    = (const float*)d_in[9];
    const float* bi    = (const float*)d_in[10];
    float* out = (float*)d_out;
    (void)in_sizes; (void)n_in; (void)out_size;

    const int smemF = FX_SMEM;                                  // 196,608
    const int smem2 = INV_SMEM_FLOATS * (int)sizeof(float);     // 64,512
    cudaFuncSetAttribute(k_fused, cudaFuncAttributeMaxDynamicSharedMemorySize, smemF);
    cudaFuncSetAttribute(k_inv,   cudaFuncAttributeMaxDynamicSharedMemorySize, smem2);

    k_prep_all<<<1046,      256>>>(x, Wi, Wr, Ws);
    k_fused   <<<NPIX / 64, 256, smemF>>>(bi, br, gamma, beta, mean, var, bs);
    k_inv     <<<NPIX / 16, 256, smem2>>>(out);
}

// round 12
// speedup vs baseline: 1.1693x; 1.0213x over previous
#include <cuda_runtime.h>
#include <cuda_bf16.h>
#include <cstdint>

// Involution2D on GB300 — round 12: round-11 fused kernel, but A (x) is
// converted fp32->bf16 hi/lo INLINE (LDG one chunk ahead -> split -> STS),
// deleting the 134MB g_x_hi/lo round-trip and shrinking prep to weights-only.

#define BB   4
#define HH_  128
#define WW_  128
#define CC   256
#define CR   64
#define KKG  144
#define FF   256
#define NPIX (BB*HH_*WW_)   // 65536

__device__ __align__(16) float g_w_buf[(size_t)NPIX * KKG];
__device__ __align__(16) float g_xi_buf[(size_t)NPIX * FF];
__device__ __align__(16) unsigned int g_wiT_hi[256 * 128];   // [f][c/2]
__device__ __align__(16) unsigned int g_wiT_lo[256 * 128];
__device__ __align__(16) unsigned int g_wrT_hi[64 * 128];    // [n][c/2]
__device__ __align__(16) unsigned int g_wrT_lo[64 * 128];
__device__ __align__(16) unsigned int g_wsT_hi[144 * 32];    // [f][k/2]
__device__ __align__(16) unsigned int g_wsT_lo[144 * 32];

#define SW(o) ((o) ^ (((o) >> 3) & 0x70))

__device__ __forceinline__ uint32_t smem_to_u32(const void* p) {
    uint32_t a;
    asm("{ .reg .u64 t; cvta.to.shared.u64 t, %1; cvt.u32.u64 %0, t; }"
        : "=r"(a) : "l"(p));
    return a;
}
__device__ __forceinline__ uint32_t bf16x2_rn(float lo, float hi) {
    uint32_t r;
    asm("cvt.rn.bf16x2.f32 %0, %1, %2;" : "=r"(r) : "f"(hi), "f"(lo));
    return r;
}
__device__ __forceinline__ void split2(float a, float b, uint32_t &hi, uint32_t &lo) {
    uint32_t ua = __float_as_uint(a), ub = __float_as_uint(b);
    hi = __byte_perm(ua, ub, 0x7632);
    lo = bf16x2_rn(a - __uint_as_float(ua & 0xFFFF0000u),
                   b - __uint_as_float(ub & 0xFFFF0000u));
}
__device__ __forceinline__ void cp_async16(uint32_t dst, const void* src) {
    asm volatile("{ .reg .u64 g; cvta.to.global.u64 g, %1;\n\t"
                 "cp.async.cg.shared.global [%0], [g], 16; }"
                 :: "r"(dst), "l"(src) : "memory");
}
__device__ __forceinline__ void cp_async16_z(uint32_t dst, const void* src, int sz) {
    asm volatile("{ .reg .u64 g; cvta.to.global.u64 g, %1;\n\t"
                 "cp.async.cg.shared.global [%0], [g], 16, %2; }"
                 :: "r"(dst), "l"(src), "r"(sz) : "memory");
}
#define CP_COMMIT() asm volatile("cp.async.commit_group;" ::: "memory")
#define CP_WAIT(n)  asm volatile("cp.async.wait_group %0;" :: "n"(n) : "memory")

__device__ __forceinline__ void ldsm4(uint32_t (&r)[4], const void* p) {
    uint32_t addr;
    asm("{ .reg .u64 t; cvta.to.shared.u64 t, %1; cvt.u32.u64 %0, t; }"
        : "=r"(addr) : "l"(p));
    asm volatile("ldmatrix.sync.aligned.m8n8.x4.shared.b16 {%0,%1,%2,%3}, [%4];"
                 : "=r"(r[0]), "=r"(r[1]), "=r"(r[2]), "=r"(r[3]) : "r"(addr));
}
__device__ __forceinline__ void mma16816(float (&d)[4], const uint32_t (&a)[4],
                                         uint32_t b0, uint32_t b1) {
    asm volatile(
        "mma.sync.aligned.m16n8k16.row.col.f32.bf16.bf16.f32 "
        "{%0,%1,%2,%3}, {%4,%5,%6,%7}, {%8,%9}, {%0,%1,%2,%3};"
        : "+f"(d[0]), "+f"(d[1]), "+f"(d[2]), "+f"(d[3])
        : "r"(a[0]), "r"(a[1]), "r"(a[2]), "r"(a[3]), "r"(b0), "r"(b1));
}

// ---------------- prep: weight transposes only (22 blocks, ~3us) ----------------
__global__ void __launch_bounds__(256)
k_prepw(const float* __restrict__ Wi, const float* __restrict__ Wr,
        const float* __restrict__ Ws)
{
    const int bid = blockIdx.x;
    const int t   = threadIdx.x;
    if (bid < 16) {
        const int idx = bid * 256 + t;
        for (int i = idx; i < 32768; i += 4096) {
            int f = i >> 7, cp = i & 127;
            uint32_t hi, lo;
            split2(Wi[(size_t)(2 * cp) * 256 + f],
                   Wi[(size_t)(2 * cp + 1) * 256 + f], hi, lo);
            g_wiT_hi[f * 128 + cp] = hi;
            g_wiT_lo[f * 128 + cp] = lo;
        }
    } else if (bid < 20) {
        const int idx = (bid - 16) * 256 + t;
        for (int i = idx; i < 8192; i += 1024) {
            int n = i >> 7, kp = i & 127;
            uint32_t hi, lo;
            split2(Wr[(2 * kp) * 64 + n], Wr[(2 * kp + 1) * 64 + n], hi, lo);
            g_wrT_hi[n * 128 + kp] = hi;
            g_wrT_lo[n * 128 + kp] = lo;
        }
    } else {
        const int idx = (bid - 20) * 256 + t;
        for (int i = idx; i < 4608; i += 512) {
            int f = i >> 5, kp = i & 31;
            uint32_t hi, lo;
            split2(Ws[(2 * kp) * 144 + f], Ws[(2 * kp + 1) * 144 + f], hi, lo);
            g_wsT_hi[f * 32 + kp] = hi;
            g_wsT_lo[f * 32 + kp] = lo;
        }
    }
}

// ---------------- fused kernel: xi AND r/w, A converted inline ----------------
// Per-buffer layout (96 KB x 2):
//   A_HI 8K | A_LO 8K | BWI_HI 32K | BWI_LO 32K | BWR_HI 8K | BWR_LO 8K
// Post-mainloop reuse of buffer-0 space:
//   WS_HI 18K | WS_LO 18K | SC 256 | SH 256 | R_HI 8K | R_LO 8K
#define FX_A_HI   0
#define FX_A_LO   8192
#define FX_BI_HI  16384
#define FX_BI_LO  49152
#define FX_BR_HI  81920
#define FX_BR_LO  90112
#define FX_BUF    98304
#define FX_SMEM   (2 * FX_BUF)   // 196608
#define FX_WS_HI  0
#define FX_WS_LO  18432
#define FX_SC     36864
#define FX_SH     37120
#define FX_R_HI   37376
#define FX_R_LO   45568

// cp.async for B operands of chunk kb into buf (one commit group by caller)
__device__ __forceinline__ void fx_issue_B(uint32_t sb, int buf, int kb, int t)
{
    const uint32_t base = sb + buf * FX_BUF;
    const uint4* gih = (const uint4*)g_wiT_hi;
    const uint4* gil = (const uint4*)g_wiT_lo;
    const uint4* grh = (const uint4*)g_wrT_hi;
    const uint4* grl = (const uint4*)g_wrT_lo;
    #pragma unroll
    for (int it = 0; it < 8; ++it) {          // B_wi: 256 rows x 8 x 16B
        int gi = t + it * 256;
        int f = gi >> 3, c = gi & 7;
        int src = f * 32 + kb * 8 + c;
        uint32_t d = SW(f * 128 + c * 16);
        cp_async16(base + FX_BI_HI + d, gih + src);
        cp_async16(base + FX_BI_LO + d, gil + src);
    }
    #pragma unroll
    for (int it = 0; it < 2; ++it) {          // B_wr: 64 rows x 8 x 16B
        int gi = t + it * 256;
        int n = gi >> 3, c = gi & 7;
        int src = n * 32 + kb * 8 + c;
        uint32_t d = SW(n * 128 + c * 16);
        cp_async16(base + FX_BR_HI + d, grh + src);
        cp_async16(base + FX_BR_LO + d, grl + src);
    }
}
// A fp32 chunk kb -> registers (4 x float4 per thread; 64px x 16 float4)
__device__ __forceinline__ void fx_ldg_A(const float* __restrict__ x, int p0,
                                         int kb, int t, float4 (&rA)[4])
{
    const float4* xs = (const float4*)x;
    #pragma unroll
    for (int it = 0; it < 4; ++it) {
        int gi = t + it * 256;
        int row = gi >> 4, c4 = gi & 15;
        rA[it] = xs[(size_t)(p0 + row) * 64 + kb * 16 + c4];
    }
}
// convert + STS A chunk from registers into buf
__device__ __forceinline__ void fx_sts_A(char* smc, int buf, int t,
                                         const float4 (&rA)[4])
{
    char* base = smc + buf * FX_BUF;
    #pragma unroll
    for (int it = 0; it < 4; ++it) {
        int gi = t + it * 256;
        int row = gi >> 4, c4 = gi & 15;
        uint32_t h0, l0, h1, l1;
        split2(rA[it].x, rA[it].y, h0, l0);
        split2(rA[it].z, rA[it].w, h1, l1);
        uint32_t d = SW(row * 128 + c4 * 8);
        *(uint2*)(base + FX_A_HI + d) = make_uint2(h0, h1);
        *(uint2*)(base + FX_A_LO + d) = make_uint2(l0, l1);
    }
}

__global__ void __launch_bounds__(256, 1)
k_fused(const float* __restrict__ x, const float* __restrict__ bi,
        const float* __restrict__ br,   const float* __restrict__ gamma,
        const float* __restrict__ beta, const float* __restrict__ mean,
        const float* __restrict__ var,  const float* __restrict__ bs)
{
    extern __shared__ char smc[];
    const uint32_t sb = smem_to_u32(smc);
    const int t    = threadIdx.x;
    const int wid  = t >> 5;
    const int lane = t & 31;
    const int p0   = blockIdx.x * 64;
    const int wm   = wid >> 2;
    const int wn   = wid & 3;

    float4 rA[4];

    // prologue: A0,A1 staged; B0,B1 in flight; A2 in regs
    fx_ldg_A(x, p0, 0, t, rA);
    fx_issue_B(sb, 0, 0, t); CP_COMMIT();
    fx_sts_A(smc, 0, t, rA);
    fx_ldg_A(x, p0, 1, t, rA);
    fx_issue_B(sb, 1, 1, t); CP_COMMIT();
    fx_sts_A(smc, 1, t, rA);
    fx_ldg_A(x, p0, 2, t, rA);

    float acc[2][8][4];     // xi accumulators
    float acc1[2][2][4];    // GEMM1 accumulators
    #pragma unroll
    for (int i = 0; i < 2; ++i) {
        #pragma unroll
        for (int j = 0; j < 8; ++j)
            #pragma unroll
            for (int q = 0; q < 4; ++q) acc[i][j][q] = 0.f;
        #pragma unroll
        for (int j = 0; j < 2; ++j)
            #pragma unroll
            for (int q = 0; q < 4; ++q) acc1[i][j][q] = 0.f;
    }

    const int lr    = lane & 15;
    const int lk    = (lane >> 4) * 16;
    const int arow  = wm * 32 + lr;
    const int brow  = wn * 64 + lr;     // xi B rows
    const int brow1 = wn * 16 + lr;     // GEMM1 B rows

    for (int kb = 0; kb < 4; ++kb) {
        if (kb < 3) CP_WAIT(1); else CP_WAIT(0);
        __syncthreads();
        char* base = smc + (kb & 1) * FX_BUF;
        #pragma unroll
        for (int k16 = 0; k16 < 4; ++k16) {
            const int ko = k16 * 32 + lk;
            uint32_t ah[2][4], al[2][4];
            #pragma unroll
            for (int i = 0; i < 2; ++i) {
                ldsm4(ah[i], base + FX_A_HI + SW((arow + i * 16) * 128 + ko));
                ldsm4(al[i], base + FX_A_LO + SW((arow + i * 16) * 128 + ko));
            }
            // GEMM1 (x @ Wr) on the same A fragments
            {
                uint32_t bh[4], bl[4];
                ldsm4(bh, base + FX_BR_HI + SW(brow1 * 128 + ko));
                ldsm4(bl, base + FX_BR_LO + SW(brow1 * 128 + ko));
                #pragma unroll
                for (int i = 0; i < 2; ++i) {
                    mma16816(acc1[i][0], ah[i], bh[0], bh[2]);
                    mma16816(acc1[i][1], ah[i], bh[1], bh[3]);
                    mma16816(acc1[i][0], al[i], bh[0], bh[2]);
                    mma16816(acc1[i][1], al[i], bh[1], bh[3]);
                    mma16816(acc1[i][0], ah[i], bl[0], bl[2]);
                    mma16816(acc1[i][1], ah[i], bl[1], bl[3]);
                }
            }
            // xi (x @ Wi)
            #pragma unroll
            for (int j = 0; j < 4; ++j) {
                uint32_t bh[4], bl[4];
                ldsm4(bh, base + FX_BI_HI + SW((brow + j * 16) * 128 + ko));
                ldsm4(bl, base + FX_BI_LO + SW((brow + j * 16) * 128 + ko));
                #pragma unroll
                for (int i = 0; i < 2; ++i) {
                    mma16816(acc[i][2*j],   ah[i], bh[0], bh[2]);
                    mma16816(acc[i][2*j+1], ah[i], bh[1], bh[3]);
                    mma16816(acc[i][2*j],   al[i], bh[0], bh[2]);
                    mma16816(acc[i][2*j+1], al[i], bh[1], bh[3]);
                    mma16816(acc[i][2*j],   ah[i], bl[0], bl[2]);
                    mma16816(acc[i][2*j+1], ah[i], bl[1], bl[3]);
                }
            }
        }
        __syncthreads();
        if (kb + 2 < 4) {
            fx_sts_A(smc, kb & 1, t, rA);            // rA holds chunk kb+2
            fx_issue_B(sb, kb & 1, kb + 2, t); CP_COMMIT();
            if (kb + 3 < 4) fx_ldg_A(x, p0, kb + 3, t, rA);
        }
    }
    // Mainloop done; buffers dead. Ws into buf0 space (hides under epilogues).
    {
        const uint4* sh = (const uint4*)g_wsT_hi;
        const uint4* sl = (const uint4*)g_wsT_lo;
        for (int i = t; i < 1152; i += 256) {
            int f = i >> 3, c = i & 7;
            uint32_t d = SW(f * 128 + c * 16);
            cp_async16(sb + FX_WS_HI + d, sh + i);
            cp_async16(sb + FX_WS_LO + d, sl + i);
        }
        CP_COMMIT();
    }
    // BN constants
    if (t < 64) {
        float s = gamma[t] * rsqrtf(var[t] + 1e-3f);
        *(float*)(smc + FX_SC + t * 4) = s;
        *(float*)(smc + FX_SH + t * 4) = (br[t] - mean[t]) * s + beta[t];
    }
    __syncthreads();

    const int g  = lane >> 2;
    const int t2 = (lane & 3) * 2;

    // epilogue 1: BN + relu on acc1, split r -> smem hi/lo
    #pragma unroll
    for (int i = 0; i < 2; ++i) {
        #pragma unroll
        for (int n8 = 0; n8 < 2; ++n8) {
            const int n0 = wn * 16 + n8 * 8 + t2;
            const float s0 = *(float*)(smc + FX_SC + n0 * 4);
            const float s1 = *(float*)(smc + FX_SC + (n0 + 1) * 4);
            const float h0 = *(float*)(smc + FX_SH + n0 * 4);
            const float h1 = *(float*)(smc + FX_SH + (n0 + 1) * 4);
            #pragma unroll
            for (int half = 0; half < 2; ++half) {
                const int m = wm * 32 + i * 16 + g + half * 8;
                float r0 = fmaxf(fmaf(acc1[i][n8][half * 2],     s0, h0), 0.f);
                float r1 = fmaxf(fmaf(acc1[i][n8][half * 2 + 1], s1, h1), 0.f);
                uint32_t hi, lo;
                split2(r0, r1, hi, lo);
                uint32_t d = SW(m * 128 + n0 * 2);
                *(uint32_t*)(smc + FX_R_HI + d) = hi;
                *(uint32_t*)(smc + FX_R_LO + d) = lo;
            }
        }
    }

    // xi epilogue: acc -> g_xi_buf (+bi); stores overlap Ws arrival
    #pragma unroll
    for (int i = 0; i < 2; ++i) {
        const int m = p0 + wm * 32 + i * 16 + g;
        #pragma unroll
        for (int j = 0; j < 8; ++j) {
            const int n = wn * 64 + j * 8 + t2;
            float b0 = bi[n], b1 = bi[n + 1];
            *(float2*)&g_xi_buf[(size_t)m * 256 + n] =
                make_float2(acc[i][j][0] + b0, acc[i][j][1] + b1);
            *(float2*)&g_xi_buf[(size_t)(m + 8) * 256 + n] =
                make_float2(acc[i][j][2] + b0, acc[i][j][3] + b1);
        }
    }

    CP_WAIT(0);
    __syncthreads();

    // GEMM2: w = r @ Ws + bs  (N=144, K=64)
    const int nblk = (wn == 3) ? 3 : 2;
    int blkid[3] = {wn, wn + 4, 8};
    float acc2[3][2][2][4];
    #pragma unroll
    for (int b = 0; b < 3; ++b)
        #pragma unroll
        for (int i = 0; i < 2; ++i)
            #pragma unroll
            for (int j = 0; j < 2; ++j)
                #pragma unroll
                for (int q = 0; q < 4; ++q) acc2[b][i][j][q] = 0.f;

    #pragma unroll
    for (int k16 = 0; k16 < 4; ++k16) {
        const int ko = k16 * 32 + lk;
        uint32_t ah[2][4], al[2][4];
        #pragma unroll
        for (int i = 0; i < 2; ++i) {
            ldsm4(ah[i], smc + FX_R_HI + SW((arow + i * 16) * 128 + ko));
            ldsm4(al[i], smc + FX_R_LO + SW((arow + i * 16) * 128 + ko));
        }
        for (int b = 0; b < nblk; ++b) {
            const int brw = blkid[b] * 16 + lr;
            uint32_t bh[4], bl[4];
            ldsm4(bh, smc + FX_WS_HI + SW(brw * 128 + ko));
            ldsm4(bl, smc + FX_WS_LO + SW(brw * 128 + ko));
            #pragma unroll
            for (int i = 0; i < 2; ++i) {
                mma16816(acc2[b][i][0], ah[i], bh[0], bh[2]);
                mma16816(acc2[b][i][1], ah[i], bh[1], bh[3]);
                mma16816(acc2[b][i][0], al[i], bh[0], bh[2]);
                mma16816(acc2[b][i][1], al[i], bh[1], bh[3]);
                mma16816(acc2[b][i][0], ah[i], bl[0], bl[2]);
                mma16816(acc2[b][i][1], ah[i], bl[1], bl[3]);
            }
        }
    }

    // epilogue 2: w -> g_w_buf (+bs)
    for (int b = 0; b < nblk; ++b) {
        #pragma unroll
        for (int j = 0; j < 2; ++j) {
            const int n = blkid[b] * 16 + j * 8 + t2;
            const float b0 = bs[n], b1 = bs[n + 1];
            #pragma unroll
            for (int i = 0; i < 2; ++i) {
                const int m = p0 + wm * 32 + i * 16 + g;
                *(float2*)&g_w_buf[(size_t)m * 144 + n] =
                    make_float2(acc2[b][i][j][0] + b0, acc2[b][i][j][1] + b1);
                *(float2*)&g_w_buf[(size_t)(m + 8) * 144 + n] =
                    make_float2(acc2[b][i][j][2] + b0, acc2[b][i][j][3] + b1);
            }
        }
    }
}

// ---------------- kernel: involution gather (round-7 proven, 16px/CTA) ----------------
#define INV_SMEM_FLOATS (3*18*256 + 16*144)

__global__ void __launch_bounds__(256)
k_inv(float* __restrict__ out)
{
    extern __shared__ float sm2[];
    float* xis = sm2;                       // [54][256]
    float* wsm = sm2 + 13824;               // [16][144]
    const uint32_t sb = smem_to_u32(sm2);

    const int t   = threadIdx.x;
    const int seg = blockIdx.x & 7;
    const int h   = (blockIdx.x >> 3) & 127;
    const int b   = blockIdx.x >> 10;
    const int w0  = seg * 16;
    const size_t prow = ((size_t)b * 128 + h) * 128;

    {
        const uint4* src = (const uint4*)(g_w_buf + (prow + w0) * 144);
        for (int i = t; i < 576; i += 256)
            cp_async16(sb + 55296 + i * 16, src + i);
    }
    for (int i = t; i < 3456; i += 256) {
        int pos = i >> 6, c4 = i & 63;
        int rr = pos / 18, cc = pos - rr * 18;
        int hhp = h - 1 + rr, wwp = w0 - 1 + cc;
        bool ok = ((unsigned)hhp < 128u) && ((unsigned)wwp < 128u);
        const uint4* s = ok
            ? (const uint4*)(g_xi_buf + (((size_t)b * 128 + hhp) * 128 + wwp) * 256) + c4
            : (const uint4*)g_xi_buf;
        cp_async16_z(sb + (uint32_t)(pos * 1024 + c4 * 16), s, ok ? 16 : 0);
    }
    CP_COMMIT();
    CP_WAIT(0);
    __syncthreads();

    const int o  = t;
    const int g  = o >> 4;
    const int fb = g * 144 + (o & 15) * 9;
    int off[9];
    #pragma unroll
    for (int kk = 0; kk < 9; kk++) {
        int flat = fb + kk;
        int kpos = flat >> 8;
        int c    = flat & 255;
        int di   = kpos / 3, dj = kpos - di * 3;
        off[kk]  = (di * 18 + dj) * 256 + c;
    }

    for (int px = 0; px < 16; px++) {
        const float* wp = &wsm[px * 144 + g * 9];
        const float* xb = &xis[px * 256];
        float acc = 0.f;
        #pragma unroll
        for (int kk = 0; kk < 9; kk++)
            acc = fmaf(wp[kk], xb[off[kk]], acc);
        out[(prow + w0 + px) * 256 + o] = acc;
    }
}

// ---------------- launch ----------------
extern "C" void kernel_launch(void* const* d_in, const int* in_sizes, int n_in,
                              void* d_out, int out_size)
{
    const float* x     = (const float*)d_in[0];
    const float* Wr    = (const float*)d_in[1];
    const float* br    = (const float*)d_in[2];
    const float* gamma = (const float*)d_in[3];
    const float* beta  = (const float*)d_in[4];
    const float* mean  = (const float*)d_in[5];
    const float* var   = (const float*)d_in[6];
    const float* Ws    = (const float*)d_in[7];
    const float* bs    = (const float*)d_in[8];
    const float* Wi    = (const float*)d_in[9];
    const float* bi    = (const float*)d_in[10];
    float* out = (float*)d_out;
    (void)in_sizes; (void)n_in; (void)out_size;

    const int smemF = FX_SMEM;                                  // 196,608
    const int smem2 = INV_SMEM_FLOATS * (int)sizeof(float);     // 64,512
    cudaFuncSetAttribute(k_fused, cudaFuncAttributeMaxDynamicSharedMemorySize, smemF);
    cudaFuncSetAttribute(k_inv,   cudaFuncAttributeMaxDynamicSharedMemorySize, smem2);

    k_prepw <<<22,         256>>>(Wi, Wr, Ws);
    k_fused <<<NPIX / 64,  256, smemF>>>(x, bi, br, gamma, beta, mean, var, bs);
    k_inv   <<<NPIX / 16,  256, smem2>>>(out);
}

// round 13
// speedup vs baseline: 1.3840x; 1.1836x over previous
#include <cuda_runtime.h>
#include <cuda_fp16.h>
#include <cstdint>

// Involution2D on GB300 — round 13: bf16 3-pass -> fp16 2-pass split.
//   x = x_hi + x_lo (fp16, residual); weights single fp16 (err ~2^-12).
//   Effects: MMA count -33%, B smem/traffic -50%, smem 196K->112K => 2 CTA/SM.
//   Addressing identical (fp16 K=64 chunk rows = 128B, same SW128 layout).

#define BB   4
#define HH_  128
#define WW_  128
#define CC   256
#define CR   64
#define KKG  144
#define FF   256
#define NPIX (BB*HH_*WW_)   // 65536

__device__ __align__(16) float g_w_buf[(size_t)NPIX * KKG];
__device__ __align__(16) float g_xi_buf[(size_t)NPIX * FF];
__device__ __align__(16) unsigned int g_wiT_h[256 * 128];   // fp16x2 [f][c/2]
__device__ __align__(16) unsigned int g_wrT_h[64 * 128];    // fp16x2 [n][c/2]
__device__ __align__(16) unsigned int g_wsT_h[144 * 32];    // fp16x2 [f][k/2]

#define SW(o) ((o) ^ (((o) >> 3) & 0x70))

__device__ __forceinline__ uint32_t smem_to_u32(const void* p) {
    uint32_t a;
    asm("{ .reg .u64 t; cvta.to.shared.u64 t, %1; cvt.u32.u64 %0, t; }"
        : "=r"(a) : "l"(p));
    return a;
}
// pack two floats to fp16x2 (a -> low, b -> high), plus exact fp16 residual
__device__ __forceinline__ uint32_t pack_h2(float a, float b) {
    __half2 H = __halves2half2(__float2half_rn(a), __float2half_rn(b));
    return *reinterpret_cast<uint32_t*>(&H);
}
__device__ __forceinline__ void split2h(float a, float b,
                                        uint32_t &hi, uint32_t &lo) {
    __half ha = __float2half_rn(a), hb = __float2half_rn(b);
    float la = a - __half2float(ha);
    float lb = b - __half2float(hb);
    __half2 H = __halves2half2(ha, hb);
    __half2 L = __halves2half2(__float2half_rn(la), __float2half_rn(lb));
    hi = *reinterpret_cast<uint32_t*>(&H);
    lo = *reinterpret_cast<uint32_t*>(&L);
}
__device__ __forceinline__ void cp_async16(uint32_t dst, const void* src) {
    asm volatile("{ .reg .u64 g; cvta.to.global.u64 g, %1;\n\t"
                 "cp.async.cg.shared.global [%0], [g], 16; }"
                 :: "r"(dst), "l"(src) : "memory");
}
__device__ __forceinline__ void cp_async16_z(uint32_t dst, const void* src, int sz) {
    asm volatile("{ .reg .u64 g; cvta.to.global.u64 g, %1;\n\t"
                 "cp.async.cg.shared.global [%0], [g], 16, %2; }"
                 :: "r"(dst), "l"(src), "r"(sz) : "memory");
}
#define CP_COMMIT() asm volatile("cp.async.commit_group;" ::: "memory")
#define CP_WAIT(n)  asm volatile("cp.async.wait_group %0;" :: "n"(n) : "memory")

__device__ __forceinline__ void ldsm4(uint32_t (&r)[4], const void* p) {
    uint32_t addr;
    asm("{ .reg .u64 t; cvta.to.shared.u64 t, %1; cvt.u32.u64 %0, t; }"
        : "=r"(addr) : "l"(p));
    asm volatile("ldmatrix.sync.aligned.m8n8.x4.shared.b16 {%0,%1,%2,%3}, [%4];"
                 : "=r"(r[0]), "=r"(r[1]), "=r"(r[2]), "=r"(r[3]) : "r"(addr));
}
__device__ __forceinline__ void mma16816(float (&d)[4], const uint32_t (&a)[4],
                                         uint32_t b0, uint32_t b1) {
    asm volatile(
        "mma.sync.aligned.m16n8k16.row.col.f32.f16.f16.f32 "
        "{%0,%1,%2,%3}, {%4,%5,%6,%7}, {%8,%9}, {%0,%1,%2,%3};"
        : "+f"(d[0]), "+f"(d[1]), "+f"(d[2]), "+f"(d[3])
        : "r"(a[0]), "r"(a[1]), "r"(a[2]), "r"(a[3]), "r"(b0), "r"(b1));
}

// ---------------- prep: weight transposes (fp16, hi only) ----------------
__global__ void __launch_bounds__(256)
k_prepw(const float* __restrict__ Wi, const float* __restrict__ Wr,
        const float* __restrict__ Ws)
{
    const int bid = blockIdx.x;
    const int t   = threadIdx.x;
    if (bid < 16) {
        const int idx = bid * 256 + t;
        for (int i = idx; i < 32768; i += 4096) {
            int f = i >> 7, cp = i & 127;
            g_wiT_h[f * 128 + cp] = pack_h2(Wi[(size_t)(2 * cp) * 256 + f],
                                            Wi[(size_t)(2 * cp + 1) * 256 + f]);
        }
    } else if (bid < 20) {
        const int idx = (bid - 16) * 256 + t;
        for (int i = idx; i < 8192; i += 1024) {
            int n = i >> 7, kp = i & 127;
            g_wrT_h[n * 128 + kp] = pack_h2(Wr[(2 * kp) * 64 + n],
                                            Wr[(2 * kp + 1) * 64 + n]);
        }
    } else {
        const int idx = (bid - 20) * 256 + t;
        for (int i = idx; i < 4608; i += 512) {
            int f = i >> 5, kp = i & 31;
            g_wsT_h[f * 32 + kp] = pack_h2(Ws[(2 * kp) * 144 + f],
                                           Ws[(2 * kp + 1) * 144 + f]);
        }
    }
}

// ---------------- fused kernel: xi AND r/w, fp16 2-pass ----------------
// Per-buffer (56 KB x 2 = 112 KB total => 2 CTA/SM):
//   A_HI 8K | A_LO 8K | BI 32K | BR 8K
// Post-mainloop reuse of buffer-0 space:
//   WS 18K | SC 256 | SH 256 | R_HI 8K | R_LO 8K
#define FX_A_HI  0
#define FX_A_LO  8192
#define FX_BI    16384
#define FX_BR    49152
#define FX_BUF   57344
#define FX_SMEM  114688
#define FX_WS    0
#define FX_SC    18432
#define FX_SH    18688
#define FX_R_HI  18944
#define FX_R_LO  27136

__device__ __forceinline__ void fx_issue_B(uint32_t sb, int buf, int kb, int t)
{
    const uint32_t base = sb + buf * FX_BUF;
    const uint4* gih = (const uint4*)g_wiT_h;
    const uint4* grh = (const uint4*)g_wrT_h;
    #pragma unroll
    for (int it = 0; it < 8; ++it) {          // B_wi: 256 rows x 8 x 16B
        int gi = t + it * 256;
        int f = gi >> 3, c = gi & 7;
        cp_async16(base + FX_BI + SW(f * 128 + c * 16), gih + f * 32 + kb * 8 + c);
    }
    #pragma unroll
    for (int it = 0; it < 2; ++it) {          // B_wr: 64 rows x 8 x 16B
        int gi = t + it * 256;
        int n = gi >> 3, c = gi & 7;
        cp_async16(base + FX_BR + SW(n * 128 + c * 16), grh + n * 32 + kb * 8 + c);
    }
}
__device__ __forceinline__ void fx_ldg_A(const float* __restrict__ x, int p0,
                                         int kb, int t, float4 (&rA)[4])
{
    const float4* xs = (const float4*)x;
    #pragma unroll
    for (int it = 0; it < 4; ++it) {
        int gi = t + it * 256;
        int row = gi >> 4, c4 = gi & 15;
        rA[it] = xs[(size_t)(p0 + row) * 64 + kb * 16 + c4];
    }
}
__device__ __forceinline__ void fx_sts_A(char* smc, int buf, int t,
                                         const float4 (&rA)[4])
{
    char* base = smc + buf * FX_BUF;
    #pragma unroll
    for (int it = 0; it < 4; ++it) {
        int gi = t + it * 256;
        int row = gi >> 4, c4 = gi & 15;
        uint32_t h0, l0, h1, l1;
        split2h(rA[it].x, rA[it].y, h0, l0);
        split2h(rA[it].z, rA[it].w, h1, l1);
        uint32_t d = SW(row * 128 + c4 * 8);
        *(uint2*)(base + FX_A_HI + d) = make_uint2(h0, h1);
        *(uint2*)(base + FX_A_LO + d) = make_uint2(l0, l1);
    }
}

__global__ void __launch_bounds__(256, 2)
k_fused(const float* __restrict__ x, const float* __restrict__ bi,
        const float* __restrict__ br,   const float* __restrict__ gamma,
        const float* __restrict__ beta, const float* __restrict__ mean,
        const float* __restrict__ var,  const float* __restrict__ bs)
{
    extern __shared__ char smc[];
    const uint32_t sb = smem_to_u32(smc);
    const int t    = threadIdx.x;
    const int wid  = t >> 5;
    const int lane = t & 31;
    const int p0   = blockIdx.x * 64;
    const int wm   = wid >> 2;
    const int wn   = wid & 3;

    float4 rA[4];

    fx_ldg_A(x, p0, 0, t, rA);
    fx_issue_B(sb, 0, 0, t); CP_COMMIT();
    fx_sts_A(smc, 0, t, rA);
    fx_ldg_A(x, p0, 1, t, rA);
    fx_issue_B(sb, 1, 1, t); CP_COMMIT();
    fx_sts_A(smc, 1, t, rA);
    fx_ldg_A(x, p0, 2, t, rA);

    float acc[2][8][4];     // xi
    float acc1[2][2][4];    // GEMM1
    #pragma unroll
    for (int i = 0; i < 2; ++i) {
        #pragma unroll
        for (int j = 0; j < 8; ++j)
            #pragma unroll
            for (int q = 0; q < 4; ++q) acc[i][j][q] = 0.f;
        #pragma unroll
        for (int j = 0; j < 2; ++j)
            #pragma unroll
            for (int q = 0; q < 4; ++q) acc1[i][j][q] = 0.f;
    }

    const int lr    = lane & 15;
    const int lk    = (lane >> 4) * 16;
    const int arow  = wm * 32 + lr;
    const int brow  = wn * 64 + lr;
    const int brow1 = wn * 16 + lr;

    for (int kb = 0; kb < 4; ++kb) {
        if (kb < 3) CP_WAIT(1); else CP_WAIT(0);
        __syncthreads();
        char* base = smc + (kb & 1) * FX_BUF;
        #pragma unroll
        for (int k16 = 0; k16 < 4; ++k16) {
            const int ko = k16 * 32 + lk;
            uint32_t ah[2][4], al[2][4];
            #pragma unroll
            for (int i = 0; i < 2; ++i) {
                ldsm4(ah[i], base + FX_A_HI + SW((arow + i * 16) * 128 + ko));
                ldsm4(al[i], base + FX_A_LO + SW((arow + i * 16) * 128 + ko));
            }
            // GEMM1: x @ Wr (2-pass)
            {
                uint32_t bv[4];
                ldsm4(bv, base + FX_BR + SW(brow1 * 128 + ko));
                #pragma unroll
                for (int i = 0; i < 2; ++i) {
                    mma16816(acc1[i][0], ah[i], bv[0], bv[2]);
                    mma16816(acc1[i][1], ah[i], bv[1], bv[3]);
                    mma16816(acc1[i][0], al[i], bv[0], bv[2]);
                    mma16816(acc1[i][1], al[i], bv[1], bv[3]);
                }
            }
            // xi: x @ Wi (2-pass)
            #pragma unroll
            for (int j = 0; j < 4; ++j) {
                uint32_t bv[4];
                ldsm4(bv, base + FX_BI + SW((brow + j * 16) * 128 + ko));
                #pragma unroll
                for (int i = 0; i < 2; ++i) {
                    mma16816(acc[i][2*j],   ah[i], bv[0], bv[2]);
                    mma16816(acc[i][2*j+1], ah[i], bv[1], bv[3]);
                    mma16816(acc[i][2*j],   al[i], bv[0], bv[2]);
                    mma16816(acc[i][2*j+1], al[i], bv[1], bv[3]);
                }
            }
        }
        __syncthreads();
        if (kb + 2 < 4) {
            fx_sts_A(smc, kb & 1, t, rA);            // rA holds chunk kb+2
            fx_issue_B(sb, kb & 1, kb + 2, t); CP_COMMIT();
            if (kb + 3 < 4) fx_ldg_A(x, p0, kb + 3, t, rA);
        }
    }
    // Ws into buf0 space (hides under epilogues)
    {
        const uint4* sh = (const uint4*)g_wsT_h;
        for (int i = t; i < 1152; i += 256) {
            int f = i >> 3, c = i & 7;
            cp_async16(sb + FX_WS + SW(f * 128 + c * 16), sh + i);
        }
        CP_COMMIT();
    }
    if (t < 64) {
        float s = gamma[t] * rsqrtf(var[t] + 1e-3f);
        *(float*)(smc + FX_SC + t * 4) = s;
        *(float*)(smc + FX_SH + t * 4) = (br[t] - mean[t]) * s + beta[t];
    }
    __syncthreads();

    const int g  = lane >> 2;
    const int t2 = (lane & 3) * 2;

    // epilogue 1: BN + relu, split r -> smem fp16 hi/lo
    #pragma unroll
    for (int i = 0; i < 2; ++i) {
        #pragma unroll
        for (int n8 = 0; n8 < 2; ++n8) {
            const int n0 = wn * 16 + n8 * 8 + t2;
            const float s0 = *(float*)(smc + FX_SC + n0 * 4);
            const float s1 = *(float*)(smc + FX_SC + (n0 + 1) * 4);
            const float h0 = *(float*)(smc + FX_SH + n0 * 4);
            const float h1 = *(float*)(smc + FX_SH + (n0 + 1) * 4);
            #pragma unroll
            for (int half = 0; half < 2; ++half) {
                const int m = wm * 32 + i * 16 + g + half * 8;
                float r0 = fmaxf(fmaf(acc1[i][n8][half * 2],     s0, h0), 0.f);
                float r1 = fmaxf(fmaf(acc1[i][n8][half * 2 + 1], s1, h1), 0.f);
                uint32_t hi, lo;
                split2h(r0, r1, hi, lo);
                uint32_t d = SW(m * 128 + n0 * 2);
                *(uint32_t*)(smc + FX_R_HI + d) = hi;
                *(uint32_t*)(smc + FX_R_LO + d) = lo;
            }
        }
    }

    // xi epilogue: acc -> g_xi_buf (+bi)
    #pragma unroll
    for (int i = 0; i < 2; ++i) {
        const int m = p0 + wm * 32 + i * 16 + g;
        #pragma unroll
        for (int j = 0; j < 8; ++j) {
            const int n = wn * 64 + j * 8 + t2;
            float b0 = bi[n], b1 = bi[n + 1];
            *(float2*)&g_xi_buf[(size_t)m * 256 + n] =
                make_float2(acc[i][j][0] + b0, acc[i][j][1] + b1);
            *(float2*)&g_xi_buf[(size_t)(m + 8) * 256 + n] =
                make_float2(acc[i][j][2] + b0, acc[i][j][3] + b1);
        }
    }

    CP_WAIT(0);
    __syncthreads();

    // GEMM2: w = r @ Ws + bs (2-pass, N=144, K=64)
    const int nblk = (wn == 3) ? 3 : 2;
    int blkid[3] = {wn, wn + 4, 8};
    float acc2[3][2][2][4];
    #pragma unroll
    for (int b = 0; b < 3; ++b)
        #pragma unroll
        for (int i = 0; i < 2; ++i)
            #pragma unroll
            for (int j = 0; j < 2; ++j)
                #pragma unroll
                for (int q = 0; q < 4; ++q) acc2[b][i][j][q] = 0.f;

    #pragma unroll
    for (int k16 = 0; k16 < 4; ++k16) {
        const int ko = k16 * 32 + lk;
        uint32_t ah[2][4], al[2][4];
        #pragma unroll
        for (int i = 0; i < 2; ++i) {
            ldsm4(ah[i], smc + FX_R_HI + SW((arow + i * 16) * 128 + ko));
            ldsm4(al[i], smc + FX_R_LO + SW((arow + i * 16) * 128 + ko));
        }
        for (int b = 0; b < nblk; ++b) {
            const int brw = blkid[b] * 16 + lr;
            uint32_t bv[4];
            ldsm4(bv, smc + FX_WS + SW(brw * 128 + ko));
            #pragma unroll
            for (int i = 0; i < 2; ++i) {
                mma16816(acc2[b][i][0], ah[i], bv[0], bv[2]);
                mma16816(acc2[b][i][1], ah[i], bv[1], bv[3]);
                mma16816(acc2[b][i][0], al[i], bv[0], bv[2]);
                mma16816(acc2[b][i][1], al[i], bv[1], bv[3]);
            }
        }
    }

    // epilogue 2: w -> g_w_buf (+bs)
    for (int b = 0; b < nblk; ++b) {
        #pragma unroll
        for (int j = 0; j < 2; ++j) {
            const int n = blkid[b] * 16 + j * 8 + t2;
            const float b0 = bs[n], b1 = bs[n + 1];
            #pragma unroll
            for (int i = 0; i < 2; ++i) {
                const int m = p0 + wm * 32 + i * 16 + g;
                *(float2*)&g_w_buf[(size_t)m * 144 + n] =
                    make_float2(acc2[b][i][j][0] + b0, acc2[b][i][j][1] + b1);
                *(float2*)&g_w_buf[(size_t)(m + 8) * 144 + n] =
                    make_float2(acc2[b][i][j][2] + b0, acc2[b][i][j][3] + b1);
            }
        }
    }
}

// ---------------- kernel: involution gather (proven, 16px/CTA) ----------------
#define INV_SMEM_FLOATS (3*18*256 + 16*144)

__global__ void __launch_bounds__(256)
k_inv(float* __restrict__ out)
{
    extern __shared__ float sm2[];
    float* xis = sm2;                       // [54][256]
    float* wsm = sm2 + 13824;               // [16][144]
    const uint32_t sb = smem_to_u32(sm2);

    const int t   = threadIdx.x;
    const int seg = blockIdx.x & 7;
    const int h   = (blockIdx.x >> 3) & 127;
    const int b   = blockIdx.x >> 10;
    const int w0  = seg * 16;
    const size_t prow = ((size_t)b * 128 + h) * 128;

    {
        const uint4* src = (const uint4*)(g_w_buf + (prow + w0) * 144);
        for (int i = t; i < 576; i += 256)
            cp_async16(sb + 55296 + i * 16, src + i);
    }
    for (int i = t; i < 3456; i += 256) {
        int pos = i >> 6, c4 = i & 63;
        int rr = pos / 18, cc = pos - rr * 18;
        int hhp = h - 1 + rr, wwp = w0 - 1 + cc;
        bool ok = ((unsigned)hhp < 128u) && ((unsigned)wwp < 128u);
        const uint4* s = ok
            ? (const uint4*)(g_xi_buf + (((size_t)b * 128 + hhp) * 128 + wwp) * 256) + c4
            : (const uint4*)g_xi_buf;
        cp_async16_z(sb + (uint32_t)(pos * 1024 + c4 * 16), s, ok ? 16 : 0);
    }
    CP_COMMIT();
    CP_WAIT(0);
    __syncthreads();

    const int o  = t;
    const int g  = o >> 4;
    const int fb = g * 144 + (o & 15) * 9;
    int off[9];
    #pragma unroll
    for (int kk = 0; kk < 9; kk++) {
        int flat = fb + kk;
        int kpos = flat >> 8;
        int c    = flat & 255;
        int di   = kpos / 3, dj = kpos - di * 3;
        off[kk]  = (di * 18 + dj) * 256 + c;
    }

    for (int px = 0; px < 16; px++) {
        const float* wp = &wsm[px * 144 + g * 9];
        const float* xb = &xis[px * 256];
        float acc = 0.f;
        #pragma unroll
        for (int kk = 0; kk < 9; kk++)
            acc = fmaf(wp[kk], xb[off[kk]], acc);
        out[(prow + w0 + px) * 256 + o] = acc;
    }
}

// ---------------- launch ----------------
extern "C" void kernel_launch(void* const* d_in, const int* in_sizes, int n_in,
                              void* d_out, int out_size)
{
    const float* x     = (const float*)d_in[0];
    const float* Wr    = (const float*)d_in[1];
    const float* br    = (const float*)d_in[2];
    const float* gamma = (const float*)d_in[3];
    const float* beta  = (const float*)d_in[4];
    const float* mean  = (const float*)d_in[5];
    const float* var   = (const float*)d_in[6];
    const float* Ws    = (const float*)d_in[7];
    const float* bs    = (const float*)d_in[8];
    const float* Wi    = (const float*)d_in[9];
    const float* bi    = (const float*)d_in[10];
    float* out = (float*)d_out;
    (void)in_sizes; (void)n_in; (void)out_size;

    const int smemF = FX_SMEM;                                  // 114,688
    const int smem2 = INV_SMEM_FLOATS * (int)sizeof(float);     // 64,512
    cudaFuncSetAttribute(k_fused, cudaFuncAttributeMaxDynamicSharedMemorySize, smemF);
    cudaFuncSetAttribute(k_inv,   cudaFuncAttributeMaxDynamicSharedMemorySize, smem2);

    k_prepw <<<22,         256>>>(Wi, Wr, Ws);
    k_fused <<<NPIX / 64,  256, smemF>>>(x, bi, br, gamma, beta, mean, var, bs);
    k_inv   <<<NPIX / 16,  256, smem2>>>(out);
}